// round 1
// baseline (speedup 1.0000x reference)
#include <cuda_runtime.h>
#include <math.h>
#include <limits.h>

// Problem constants
#define Bv 8
#define Vv 8
#define Nv 1000
#define Dv 256
#define Hv 8
#define KSv 32
#define D3 768          // 3*D
#define FNv 8
#define TILE 128        // nodes per attention block
#define NTILE 8         // ceil(1000/128)
#define T2 4            // logits tiles: ceil(1000/256)

// ---------------- scratch (__device__ globals; no allocation allowed) ----------------
__device__ float g_A8[D3 * 8];              // fused affine map: nde = A8[:, :7]@feats + A8[:,7]*flag
__device__ int   g_mask_mode;               // 0=uint8/bool, 1=int32, 2=float32
__device__ float g_query[Bv * Vv * Dv];
__device__ float g_concat[Bv * Vv * Dv];
__device__ float g_fQ[Bv * Vv * Dv];
__device__ float g_am[Hv * Bv * Vv * NTILE];
__device__ float g_as[Hv * Bv * Vv * NTILE];
__device__ float g_aacc[Hv * Bv * Vv * NTILE * KSv];
__device__ float g_lm[Bv * Vv * T2];
__device__ float g_ls[Bv * Vv * T2];
__device__ int   g_li[Bv * Vv * T2];

// ---------------- helpers ----------------
__device__ __forceinline__ bool mask_at(const void* m, int mode, int idx) {
    if (mode == 0) return ((const unsigned char*)m)[idx] != 0;
    if (mode == 1) return ((const int*)m)[idx] != 0;
    return ((const float*)m)[idx] != 0.0f;
}
__device__ __forceinline__ float warpMax(float v) {
    #pragma unroll
    for (int o = 16; o; o >>= 1) v = fmaxf(v, __shfl_xor_sync(0xffffffffu, v, o));
    return v;
}
__device__ __forceinline__ float warpSum(float v) {
    #pragma unroll
    for (int o = 16; o; o >>= 1) v += __shfl_xor_sync(0xffffffffu, v, o);
    return v;
}

// ---------------- K0: A8 = W1 + W2[:, :768] @ W1 ; A8[:,7] = W2[:,768]; mask sniff ----------------
__global__ void k0_prepA(const float* __restrict__ W1, const float* __restrict__ W2,
                         const void* __restrict__ mask) {
    int j = blockIdx.x;
    if (j == D3) {
        if (threadIdx.x == 0) {
            // Deterministic dtype sniff on first 64 bytes. bool bytes are iid {0,1}
            // (P(all high bytes zero) ~ 0.3^48); int32 dwords are {0,1}; float32
            // dwords are {0, 0x3F800000} and element 0 is guaranteed True.
            const unsigned int* w = (const unsigned int*)mask;
            bool allF = true, allI = true;
            for (int i = 0; i < 16; i++) {
                unsigned int x = w[i];
                if (x != 0x3F800000u && x != 0u) allF = false;
                if (x > 1u) allI = false;
            }
            g_mask_mode = allF ? 2 : (allI ? 1 : 0);
        }
        return;
    }
    __shared__ float red[7][256];
    float p[7] = {0, 0, 0, 0, 0, 0, 0};
    const float* w2row = W2 + (size_t)j * 769;
    for (int k = threadIdx.x; k < D3; k += 256) {
        float w2 = w2row[k];
        const float* w1r = W1 + k * 7;
        #pragma unroll
        for (int i = 0; i < 7; i++) p[i] += w2 * w1r[i];
    }
    #pragma unroll
    for (int i = 0; i < 7; i++) red[i][threadIdx.x] = p[i];
    __syncthreads();
    if (threadIdx.x < 7) {
        float s = 0.f;
        for (int t = 0; t < 256; t++) s += red[threadIdx.x][t];
        g_A8[j * 8 + threadIdx.x] = W1[j * 7 + threadIdx.x] + s;
    } else if (threadIdx.x == 7) {
        g_A8[j * 8 + 7] = w2row[768];
    }
}

// ---------------- K1: query = fixed_context + pcs @ [prev; veh] ----------------
__global__ void k1_query(const float* __restrict__ fixedc, const float* __restrict__ prev,
                         const float* __restrict__ veh, const float* __restrict__ pcs) {
    int bv = blockIdx.x;
    int b = bv / Vv;
    int tid = threadIdx.x;
    __shared__ float scv[264];
    scv[tid] = prev[(size_t)bv * Dv + tid];
    if (tid < 8) scv[256 + tid] = veh[bv * 8 + tid];
    __syncthreads();
    const float* wr = pcs + (size_t)tid * 264;
    float dot = 0.f;
    #pragma unroll 8
    for (int j = 0; j < 264; j++) dot += wr[j] * scv[j];
    g_query[(size_t)bv * Dv + tid] = fixedc[b * Dv + tid] + dot;
}

// ---------------- K2: fused attention partials (warp = head, lane = node) ----------------
__global__ void k2_attn(const float* __restrict__ gKs, const float* __restrict__ gVs,
                        const float* __restrict__ ndf, const void* __restrict__ mask) {
    int t = blockIdx.x, v = blockIdx.y, b = blockIdx.z;
    int tid = threadIdx.x, h = tid >> 5, lane = tid & 31;

    __shared__ float smem[8448];          // phase1: A8(6144) + Q(256); phase2: 8 warps x 1056 transpose
    float* sA = smem;
    float* sQ = smem + 6144;
    for (int i = tid; i < 6144; i += 256) sA[i] = g_A8[i];
    sQ[tid] = g_query[((size_t)b * Vv + v) * Dv + tid];
    __syncthreads();

    const int mode = g_mask_mode;
    const float* sQh = sQ + h * 32;
    const float4* aK4 = reinterpret_cast<const float4*>(sA + (256 + h * 32) * 8);
    const float4* aV4 = reinterpret_cast<const float4*>(sA + (h * 32) * 8);

    float m = -INFINITY, s = 0.f;
    float acc[32];
    #pragma unroll
    for (int k = 0; k < 32; k++) acc[k] = 0.f;

    const int mbase = (b * Vv + v) * Nv;
    #pragma unroll
    for (int it = 0; it < 4; it++) {
        int n = t * TILE + it * 32 + lane;
        if (n >= Nv) continue;
        if (!mask_at(mask, mode, mbase + n)) continue;

        const float4* fp4 = reinterpret_cast<const float4*>(ndf + (size_t)(mbase + n) * 8);
        float4 fA = fp4[0], fB = fp4[1];
        float f0 = fA.x, f1 = fA.y, f2 = fA.z, f3 = fA.w;
        float f4 = fB.x, f5 = fB.y, f6 = fB.z, f7 = fB.w;

        // compat = (gQ . (gKs + A8K @ f)) / sqrt(32)
        const float4* kp4 = reinterpret_cast<const float4*>(gKs + (((size_t)(h * Bv + b)) * Nv + n) * KSv);
        float dot = 0.f;
        #pragma unroll
        for (int k4 = 0; k4 < 8; k4++) {
            float4 kk = kp4[k4];
            float kv[4] = {kk.x, kk.y, kk.z, kk.w};
            #pragma unroll
            for (int u = 0; u < 4; u++) {
                int k = k4 * 4 + u;
                float4 a0 = aK4[k * 2], a1 = aK4[k * 2 + 1];
                float g = a0.x * f0 + a0.y * f1 + a0.z * f2 + a0.w * f3
                        + a1.x * f4 + a1.y * f5 + a1.z * f6 + a1.w * f7;
                dot += sQh[k] * (kv[u] + g);
            }
        }
        float c = dot * 0.17677669529663687f;   // 1/sqrt(32)

        if (c > m) {
            float fac = expf(m - c);            // expf(-inf)=0 on first hit
            s *= fac;
            #pragma unroll
            for (int k = 0; k < 32; k++) acc[k] *= fac;
            m = c;
        }
        float w = expf(c - m);
        s += w;

        const float4* vp4 = reinterpret_cast<const float4*>(gVs + (((size_t)(h * Bv + b)) * Nv + n) * KSv);
        #pragma unroll
        for (int k4 = 0; k4 < 8; k4++) {
            float4 vv = vp4[k4];
            float va[4] = {vv.x, vv.y, vv.z, vv.w};
            #pragma unroll
            for (int u = 0; u < 4; u++) {
                int k = k4 * 4 + u;
                float4 a0 = aV4[k * 2], a1 = aV4[k * 2 + 1];
                float g = a0.x * f0 + a0.y * f1 + a0.z * f2 + a0.w * f3
                        + a1.x * f4 + a1.y * f5 + a1.z * f6 + a1.w * f7;
                acc[k] += w * (va[u] + g);
            }
        }
    }

    __syncthreads();   // A8/Q dead; reuse smem for per-warp transpose
    float Mw = warpMax(m);
    float sc = (Mw == -INFINITY) ? 0.f : expf(m - Mw);
    float Sw = warpSum(s * sc);
    float* sw = smem + h * 1056;
    #pragma unroll
    for (int k = 0; k < 32; k++) sw[k * 33 + lane] = acc[k] * sc;
    __syncwarp();
    float col = 0.f;
    #pragma unroll
    for (int l = 0; l < 32; l++) col += sw[lane * 33 + l];

    int p = ((h * Bv + b) * Vv + v) * NTILE + t;
    if (lane == 0) { g_am[p] = Mw; g_as[p] = Sw; }
    g_aacc[p * 32 + lane] = col;
}

// ---------------- K3: combine partials over (v, tiles) per (h,b); write concat heads --------
__global__ void k3_combine() {
    int hb = blockIdx.x;   // h*B + b
    int tid = threadIdx.x;
    __shared__ float sm_[64];
    __shared__ float ss_[64];
    __shared__ float sInvS;
    if (tid < 64) { sm_[tid] = g_am[hb * 64 + tid]; ss_[tid] = g_as[hb * 64 + tid]; }
    __syncthreads();
    if (tid == 0) {
        float M = -INFINITY;
        for (int q = 0; q < 64; q++) M = fmaxf(M, sm_[q]);
        float S = 0.f;
        for (int q = 0; q < 64; q++) {
            float sc = (sm_[q] == -INFINITY) ? 0.f : expf(sm_[q] - M);
            S += ss_[q] * sc;
            sm_[q] = sc;   // reuse as scale
        }
        sInvS = 1.0f / S;
    }
    __syncthreads();
    int v = tid >> 5, k = tid & 31;
    float sum = 0.f;
    #pragma unroll
    for (int t = 0; t < NTILE; t++)
        sum += g_aacc[((hb * Vv + v) * NTILE + t) * 32 + k] * sm_[v * NTILE + t];
    int b = hb & 7, h = hb >> 3;
    g_concat[((size_t)(b * Vv + v)) * Dv + h * 32 + k] = sum * sInvS;
}

// ---------------- K4: final_Q = po @ concat ----------------
__global__ void k4_finalQ(const float* __restrict__ po) {
    int bv = blockIdx.x;
    int tid = threadIdx.x;
    __shared__ float sC[256];
    sC[tid] = g_concat[(size_t)bv * Dv + tid];
    __syncthreads();
    const float* wr = po + (size_t)tid * Dv;
    float dot = 0.f;
    #pragma unroll 8
    for (int j = 0; j < 256; j++) dot += wr[j] * sC[j];
    g_fQ[(size_t)bv * Dv + tid] = dot;
}

// ---------------- K5: logits partials (max/argmax/sumexp per block) ----------------
__global__ void k5_logits(const float* __restrict__ lKs, const float* __restrict__ ndf,
                          const void* __restrict__ mask) {
    int t = blockIdx.x, v = blockIdx.y, b = blockIdx.z;
    int tid = threadIdx.x;
    __shared__ float sA3[2048];   // A8 rows 512..767
    __shared__ float sFQ[256];
    __shared__ float sv[256];
    __shared__ int   si[256];
    for (int i = tid; i < 2048; i += 256) sA3[i] = g_A8[4096 + i];
    sFQ[tid] = g_fQ[((size_t)(b * Vv + v)) * Dv + tid];
    __syncthreads();

    const int mode = g_mask_mode;
    int n = t * 256 + tid;
    float val = -INFINITY;
    int gidx = INT_MAX;
    if (n < Nv) {
        gidx = v * Nv + n;
        int midx = (b * Vv + v) * Nv + n;
        if (mask_at(mask, mode, midx)) {
            const float4* fp4 = reinterpret_cast<const float4*>(ndf + (size_t)midx * 8);
            float4 fA = fp4[0], fB = fp4[1];
            float f0 = fA.x, f1 = fA.y, f2 = fA.z, f3 = fA.w;
            float f4 = fB.x, f5 = fB.y, f6 = fB.z, f7 = fB.w;
            const float4* kp4 = reinterpret_cast<const float4*>(lKs + ((size_t)b * Nv + n) * Dv);
            float dot = 0.f;
            #pragma unroll 4
            for (int c4 = 0; c4 < 64; c4++) {
                float4 kk = kp4[c4];
                float kv[4] = {kk.x, kk.y, kk.z, kk.w};
                #pragma unroll
                for (int u = 0; u < 4; u++) {
                    int c = c4 * 4 + u;
                    const float4* a = reinterpret_cast<const float4*>(sA3 + c * 8);
                    float4 a0 = a[0], a1 = a[1];
                    float g = a0.x * f0 + a0.y * f1 + a0.z * f2 + a0.w * f3
                            + a1.x * f4 + a1.y * f5 + a1.z * f6 + a1.w * f7;
                    dot += sFQ[c] * (kv[u] + g);
                }
            }
            val = tanhf(dot * 0.0625f) * 10.0f;   // /sqrt(256), tanh-clip
        }
    }
    sv[tid] = val; si[tid] = gidx;
    __syncthreads();
    for (int st = 128; st; st >>= 1) {
        if (tid < st) {
            float o = sv[tid + st]; int oi = si[tid + st];
            if (o > sv[tid] || (o == sv[tid] && oi < si[tid])) { sv[tid] = o; si[tid] = oi; }
        }
        __syncthreads();
    }
    float M = sv[0]; int am = si[0];
    __syncthreads();
    float e = (val == -INFINITY || M == -INFINITY) ? 0.f : expf(val - M);
    sv[tid] = e;
    __syncthreads();
    for (int st = 128; st; st >>= 1) {
        if (tid < st) sv[tid] += sv[tid + st];
        __syncthreads();
    }
    if (tid == 0) {
        int p = (b * Vv + v) * T2 + t;
        g_lm[p] = M; g_li[p] = am;
        g_ls[p] = (M == -INFINITY) ? 0.f : sv[0];
    }
}

// ---------------- K6: per-batch combine -> outputs ----------------
__global__ void k6_final(float* __restrict__ out, int out_size) {
    int tid = threadIdx.x;
    int b = tid >> 5, lane = tid & 31;    // 32 partials per batch (V=8 * T2=4)
    __shared__ float sS[8];
    __shared__ int   sOp[8];
    float m = g_lm[b * 32 + lane];
    float s = g_ls[b * 32 + lane];
    int   ix = g_li[b * 32 + lane];
    float M = m; int I = ix;
    #pragma unroll
    for (int o = 16; o; o >>= 1) {
        float om = __shfl_xor_sync(0xffffffffu, M, o);
        int   oi = __shfl_xor_sync(0xffffffffu, I, o);
        if (om > M || (om == M && oi < I)) { M = om; I = oi; }
    }
    float term = (m == -INFINITY) ? 0.f : s * expf(m - M);
    float S = warpSum(term);
    if (lane == 0) { sS[b] = S; sOp[b] = I; }
    __syncthreads();
    if (tid < 8) {
        int op = sOp[tid];
        float Sb = sS[tid];
        if (tid < out_size)      out[tid]      = (float)(op / Nv);   // selected_vecs
        if (8 + tid < out_size)  out[8 + tid]  = (float)(op % Nv);   // selected_nodes
        if (16 + tid < out_size) out[16 + tid] = -logf(Sb);          // logprob
    }
    if (tid == 0 && out_size > 24) {
        float ent = 0.f;
        for (int i = 0; i < 8; i++) ent += logf(sS[i]) / sS[i];      // -sum(prob*logprob)
        out[24] = ent;
    }
}

// ---------------- launch ----------------
extern "C" void kernel_launch(void* const* d_in, const int* in_sizes, int n_in,
                              void* d_out, int out_size) {
    (void)in_sizes; (void)n_in;
    // Input order per metadata: 0 node_embeddings(unused), 1 fixed_context,
    // 2 prev_node_embeddings, 3 node_dynamic_features, 4 vehicle_dynamic_features,
    // 5 glimpse_V_static, 6 glimpse_K_static, 7 logit_K_static, 8 feasibility_mask,
    // 9 pcs_weight, 10 pns1_weight, 11 pns2_weight, 12 po_weight
    const float* fixedc = (const float*)d_in[1];
    const float* prev   = (const float*)d_in[2];
    const float* ndf    = (const float*)d_in[3];
    const float* veh    = (const float*)d_in[4];
    const float* gVs    = (const float*)d_in[5];
    const float* gKs    = (const float*)d_in[6];
    const float* lKs    = (const float*)d_in[7];
    const void*  mask   = d_in[8];
    const float* pcs    = (const float*)d_in[9];
    const float* W1     = (const float*)d_in[10];
    const float* W2     = (const float*)d_in[11];
    const float* po     = (const float*)d_in[12];

    k0_prepA<<<D3 + 1, 256>>>(W1, W2, mask);
    k1_query<<<Bv * Vv, 256>>>(fixedc, prev, veh, pcs);
    k2_attn<<<dim3(NTILE, Vv, Bv), 256>>>(gKs, gVs, ndf, mask);
    k3_combine<<<Hv * Bv, 256>>>();
    k4_finalQ<<<Bv * Vv, 256>>>(po);
    k5_logits<<<dim3(T2, Vv, Bv), 256>>>(lKs, ndf, mask);
    k6_final<<<1, 256>>>((float*)d_out, out_size);
}

// round 4
// speedup vs baseline: 1.3326x; 1.3326x over previous
#include <cuda_runtime.h>
#include <math.h>
#include <limits.h>

// Problem constants
#define Bv 8
#define Vv 8
#define Nv 1000
#define Dv 256
#define Hv 8
#define KSv 32
#define D3 768
#define SCALE_K 0.17677669529663687f   // 1/sqrt(32)
#define SCALE_D 0.0625f                // 1/sqrt(256)

// ---------------- scratch ----------------
__device__ float g_A8[D3 * 8];      // nde row j = A8[j][0..6]@feats + A8[j][7]*flag
__device__ int   g_mask_mode;       // 0=uint8/bool, 1=int32, 2=float32
__device__ float g_query[64 * Dv];
__device__ float g_fQ[64 * Dv];     // pre-scaled by 1/16
__device__ float g_am[4096];        // (h*8+b)*64 + v*8 + t
__device__ float g_as[4096];
__device__ float g_aacc[4096 * 32];
__device__ float g_lm[64];          // b*8 + t
__device__ float g_ls[64];
__device__ int   g_li[64];

__device__ __forceinline__ bool mask_at(const void* m, int mode, int idx) {
    if (mode == 0) return ((const unsigned char*)m)[idx] != 0;
    if (mode == 1) return ((const int*)m)[idx] != 0;
    return ((const float*)m)[idx] != 0.0f;
}
__device__ __forceinline__ float warpMax(float v) {
    #pragma unroll
    for (int o = 16; o; o >>= 1) v = fmaxf(v, __shfl_xor_sync(0xffffffffu, v, o));
    return v;
}
__device__ __forceinline__ float warpSum(float v) {
    #pragma unroll
    for (int o = 16; o; o >>= 1) v += __shfl_xor_sync(0xffffffffu, v, o);
    return v;
}

// ---------------- kA: A8 build (blocks 0..767), mask sniff (768), query (769..832) ----------
__global__ void kA(const float* __restrict__ W1, const float* __restrict__ W2,
                   const void* __restrict__ mask, const float* __restrict__ fixedc,
                   const float* __restrict__ prev, const float* __restrict__ veh,
                   const float* __restrict__ pcs) {
    int j = blockIdx.x;
    int tid = threadIdx.x;
    if (j < D3) {
        float p[7] = {0, 0, 0, 0, 0, 0, 0};
        const float* w2row = W2 + (size_t)j * 769;
        for (int k = tid; k < D3; k += 256) {
            float w2 = w2row[k];
            const float* w1r = W1 + k * 7;
            #pragma unroll
            for (int i = 0; i < 7; i++) p[i] += w2 * w1r[i];
        }
        #pragma unroll
        for (int i = 0; i < 7; i++) p[i] = warpSum(p[i]);
        __shared__ float red[8][7];
        if ((tid & 31) == 0)
            #pragma unroll
            for (int i = 0; i < 7; i++) red[tid >> 5][i] = p[i];
        __syncthreads();
        if (tid < 7) {
            float s = 0.f;
            #pragma unroll
            for (int w = 0; w < 8; w++) s += red[w][tid];
            g_A8[j * 8 + tid] = W1[j * 7 + tid] + s;
        } else if (tid == 7) {
            g_A8[j * 8 + 7] = w2row[768];
        }
    } else if (j == D3) {
        if (tid == 0) {
            const unsigned int* w = (const unsigned int*)mask;
            bool allF = true, allI = true;
            for (int i = 0; i < 16; i++) {
                unsigned int x = w[i];
                if (x != 0x3F800000u && x != 0u) allF = false;
                if (x > 1u) allI = false;
            }
            g_mask_mode = allF ? 2 : (allI ? 1 : 0);
        }
    } else {
        int bv = j - (D3 + 1);
        __shared__ float scv[264];
        scv[tid] = prev[(size_t)bv * Dv + tid];
        if (tid < 8) scv[256 + tid] = veh[bv * 8 + tid];
        __syncthreads();
        const float* wr = pcs + (size_t)tid * 264;
        float dot = 0.f;
        #pragma unroll 8
        for (int jj = 0; jj < 264; jj++) dot += wr[jj] * scv[jj];
        g_query[(size_t)bv * Dv + tid] = fixedc[(bv >> 3) * Dv + tid] + dot;
    }
}

// ---------------- kB: fused attention partials (warp=head, lane=node) --------------
__global__ void __launch_bounds__(256) kB(const float* __restrict__ gKs,
                                          const float* __restrict__ gVs,
                                          const float* __restrict__ ndf,
                                          const void* __restrict__ mask) {
    int t = blockIdx.x, v = blockIdx.y, b = blockIdx.z;
    int tid = threadIdx.x, h = tid >> 5, lane = tid & 31;
    __shared__ float sQ[256];       // scaled query
    __shared__ float sAV[2048];     // A8 rows 0..255 (gV part)
    __shared__ float sF[128 * 12];  // ndf tile + mask flag (slot 8), stride 12 (bank-safe)
    __shared__ float sT[8192];      // per-warp 32x32 swizzled transpose

    sQ[tid] = g_query[((size_t)(b * Vv + v)) * Dv + tid] * SCALE_K;
    for (int i = tid; i < 2048; i += 256) sAV[i] = g_A8[i];
    int mode = g_mask_mode;
    {
        int nl = tid >> 1, hh = tid & 1;
        int n = t * 128 + nl;
        int midx = ((b * Vv + v)) * Nv + n;
        float4 fv = make_float4(0, 0, 0, 0);
        if (n < Nv) fv = ((const float4*)ndf)[((size_t)midx << 1) + hh];
        *(float4*)&sF[nl * 12 + hh * 4] = fv;
        if (hh == 0) sF[nl * 12 + 8] = (n < Nv && mask_at(mask, mode, midx)) ? 1.f : 0.f;
    }
    __syncthreads();

    // qa = (scaled q)ᵀ A8K  (once per warp)
    float qa[8];
    {
        float qk = sQ[h * 32 + lane];
        const float4* ar = (const float4*)(g_A8 + (256 + h * 32 + lane) * 8);
        float4 a0 = ar[0], a1 = ar[1];
        float av[8] = {a0.x, a0.y, a0.z, a0.w, a1.x, a1.y, a1.z, a1.w};
        #pragma unroll
        for (int jj = 0; jj < 8; jj++) qa[jj] = warpSum(qk * av[jj]);
    }

    float m = -INFINITY, s = 0.f;
    float fw[8];
    float acc[32];
    #pragma unroll
    for (int jj = 0; jj < 8; jj++) fw[jj] = 0.f;
    #pragma unroll
    for (int k = 0; k < 32; k++) acc[k] = 0.f;

    size_t kvbase = (size_t)(h * Bv + b) * Nv * KSv;
    #pragma unroll
    for (int it = 0; it < 4; it++) {
        int nl = it * 32 + lane;
        int n = t * 128 + nl;
        if (sF[nl * 12 + 8] != 0.f) {
            const float* fp = &sF[nl * 12];
            float f0 = fp[0], f1 = fp[1], f2 = fp[2], f3 = fp[3];
            float f4 = fp[4], f5 = fp[5], f6 = fp[6], f7 = fp[7];
            const float4* kp = (const float4*)(gKs + kvbase + (size_t)n * KSv);
            float d0 = 0, d1 = 0, d2 = 0, d3 = 0;
            #pragma unroll
            for (int c4 = 0; c4 < 8; c4++) {
                float4 kk = kp[c4];
                d0 += sQ[h * 32 + c4 * 4 + 0] * kk.x;
                d1 += sQ[h * 32 + c4 * 4 + 1] * kk.y;
                d2 += sQ[h * 32 + c4 * 4 + 2] * kk.z;
                d3 += sQ[h * 32 + c4 * 4 + 3] * kk.w;
            }
            float c = (d0 + d1) + (d2 + d3)
                    + qa[0] * f0 + qa[1] * f1 + qa[2] * f2 + qa[3] * f3
                    + qa[4] * f4 + qa[5] * f5 + qa[6] * f6 + qa[7] * f7;
            float mn = fmaxf(m, c);
            float fac = __expf(m - mn);
            float w = __expf(c - mn);
            m = mn;
            s = s * fac + w;
            const float4* vp = (const float4*)(gVs + kvbase + (size_t)n * KSv);
            #pragma unroll
            for (int c4 = 0; c4 < 8; c4++) {
                float4 vv = vp[c4];
                acc[c4 * 4 + 0] = acc[c4 * 4 + 0] * fac + w * vv.x;
                acc[c4 * 4 + 1] = acc[c4 * 4 + 1] * fac + w * vv.y;
                acc[c4 * 4 + 2] = acc[c4 * 4 + 2] * fac + w * vv.z;
                acc[c4 * 4 + 3] = acc[c4 * 4 + 3] * fac + w * vv.w;
            }
            fw[0] = fw[0] * fac + w * f0; fw[1] = fw[1] * fac + w * f1;
            fw[2] = fw[2] * fac + w * f2; fw[3] = fw[3] * fac + w * f3;
            fw[4] = fw[4] * fac + w * f4; fw[5] = fw[5] * fac + w * f5;
            fw[6] = fw[6] * fac + w * f6; fw[7] = fw[7] * fac + w * f7;
        }
    }

    // warp-level combine
    float Mw = warpMax(m);
    float sc = (m == -INFINITY) ? 0.f : __expf(m - Mw);
    float Sw = warpSum(s * sc);
    float fwt[8];
    #pragma unroll
    for (int jj = 0; jj < 8; jj++) fwt[jj] = warpSum(fw[jj] * sc);

    float* sw = sT + h * 1024;
    #pragma unroll
    for (int k = 0; k < 32; k++) sw[k * 32 + ((lane + k) & 31)] = acc[k] * sc;
    __syncwarp();
    float col = 0.f;
    #pragma unroll
    for (int l = 0; l < 32; l++) col += sw[lane * 32 + ((l + lane) & 31)];
    const float* avr = &sAV[(h * 32 + lane) * 8];
    #pragma unroll
    for (int jj = 0; jj < 8; jj++) col += avr[jj] * fwt[jj];

    int p = ((h * Bv + b) * Vv + v) * 8 + t;
    if (lane == 0) { g_am[p] = Mw; g_as[p] = Sw; }
    g_aacc[p * 32 + lane] = col;
}

// ---------------- kC: combine + final_Q (block per (b,v), warp per head) ----------
__global__ void kC(const float* __restrict__ po) {
    int bv = blockIdx.x;
    int b = bv >> 3, v = bv & 7;
    int tid = threadIdx.x, h = tid >> 5, lane = tid & 31;
    __shared__ float sC[256];
    int base = (h * Bv + b) * 64;
    float m1 = g_am[base + lane], m2 = g_am[base + 32 + lane];
    float M = warpMax(fmaxf(m1, m2));
    float ss = g_as[base + lane] * __expf(m1 - M) + g_as[base + 32 + lane] * __expf(m2 - M);
    float S = warpSum(ss);
    float invS = 1.f / S;
    float sum = 0.f;
    #pragma unroll
    for (int tt = 0; tt < 8; tt++) {
        int pp = base + v * 8 + tt;
        float mt = g_am[pp];
        sum += g_aacc[pp * 32 + lane] * __expf(mt - M);
    }
    sC[h * 32 + lane] = sum * invS;
    __syncthreads();
    const float* wr = po + (size_t)tid * Dv;
    float dot = 0.f;
    #pragma unroll 8
    for (int jj = 0; jj < 256; jj++) dot += wr[jj] * sC[jj];
    g_fQ[(size_t)bv * Dv + tid] = dot * SCALE_D;   // pre-scaled for logits
}

// ---------------- kD: logits, all v per node, block=(tile128, b) ----------------
__global__ void __launch_bounds__(256) kD(const float* __restrict__ lKs,
                                          const float* __restrict__ ndf,
                                          const void* __restrict__ mask) {
    int t = blockIdx.x, b = blockIdx.y;
    int tid = threadIdx.x, w = tid >> 5, lane = tid & 31;
    __shared__ float sFQ[2048];
    __shared__ float sQA[64];
    __shared__ float sRm[8]; __shared__ int sRi[8]; __shared__ float sRs[8];
    __shared__ float sM; __shared__ int sI;

    #pragma unroll
    for (int i = 0; i < 8; i++) {
        int c = lane + i * 32;
        sFQ[w * 256 + c] = g_fQ[((size_t)(b * Vv + w)) * Dv + c];
    }
    __syncthreads();
    {   // qa3 = (scaled fQ_v)ᵀ A8_lK,  warp w = v
        float p8[8] = {0, 0, 0, 0, 0, 0, 0, 0};
        for (int c = lane; c < 256; c += 32) {
            float fq = sFQ[w * 256 + c];
            const float4* ar = (const float4*)(g_A8 + (512 + c) * 8);
            float4 a0 = ar[0], a1 = ar[1];
            p8[0] += fq * a0.x; p8[1] += fq * a0.y; p8[2] += fq * a0.z; p8[3] += fq * a0.w;
            p8[4] += fq * a1.x; p8[5] += fq * a1.y; p8[6] += fq * a1.z; p8[7] += fq * a1.w;
        }
        #pragma unroll
        for (int jj = 0; jj < 8; jj++) p8[jj] = warpSum(p8[jj]);
        if (lane < 8) sQA[w * 8 + lane] = p8[lane];
    }
    __syncthreads();

    int mode = g_mask_mode;
    int half = lane >> 4;
    int n = t * 128 + w * 16 + (lane & 15);
    bool valid = n < Nv;
    float dv[8] = {0, 0, 0, 0, 0, 0, 0, 0};
    if (valid) {
        const float4* kp = (const float4*)(lKs + ((size_t)b * Nv + n) * Dv) + half * 32;
        const float4* fq4 = (const float4*)sFQ;
        int cbase = half * 32;
        #pragma unroll 4
        for (int c4 = 0; c4 < 32; c4++) {
            float4 kk = kp[c4];
            #pragma unroll
            for (int vv = 0; vv < 8; vv++) {
                float4 fq = fq4[vv * 64 + cbase + c4];
                dv[vv] += fq.x * kk.x + fq.y * kk.y + fq.z * kk.z + fq.w * kk.w;
            }
        }
    }
    #pragma unroll
    for (int vv = 0; vv < 8; vv++) dv[vv] += __shfl_xor_sync(0xffffffffu, dv[vv], 16);

    float vals[8];
    float best = -INFINITY; int bidx = INT_MAX;
    if (half == 0 && valid) {
        #pragma unroll
        for (int vv = 0; vv < 8; vv++) {
            float val = -INFINITY;
            int midx = (b * Vv + vv) * Nv + n;
            if (mask_at(mask, mode, midx)) {
                const float4* fp = (const float4*)(ndf + (size_t)midx * 8);
                float4 fA = fp[0], fB = fp[1];
                const float* qa = &sQA[vv * 8];
                float e = dv[vv]
                        + qa[0] * fA.x + qa[1] * fA.y + qa[2] * fA.z + qa[3] * fA.w
                        + qa[4] * fB.x + qa[5] * fB.y + qa[6] * fB.z + qa[7] * fB.w;
                val = tanhf(e) * 10.0f;
            }
            vals[vv] = val;
            if (val > best) { best = val; bidx = vv * Nv + n; }
        }
    } else {
        #pragma unroll
        for (int vv = 0; vv < 8; vv++) vals[vv] = -INFINITY;
    }
    #pragma unroll
    for (int o = 16; o; o >>= 1) {
        float om = __shfl_xor_sync(0xffffffffu, best, o);
        int   oi = __shfl_xor_sync(0xffffffffu, bidx, o);
        if (om > best || (om == best && oi < bidx)) { best = om; bidx = oi; }
    }
    if (lane == 0) { sRm[w] = best; sRi[w] = bidx; }
    __syncthreads();
    if (tid == 0) {
        float M = -INFINITY; int I = INT_MAX;
        for (int i = 0; i < 8; i++)
            if (sRm[i] > M || (sRm[i] == M && sRi[i] < I)) { M = sRm[i]; I = sRi[i]; }
        sM = M; sI = I;
    }
    __syncthreads();
    float M = sM;
    float es = 0.f;
    if (half == 0 && valid) {
        #pragma unroll
        for (int vv = 0; vv < 8; vv++)
            if (vals[vv] != -INFINITY) es += __expf(vals[vv] - M);
    }
    es = warpSum(es);
    if (lane == 0) sRs[w] = es;
    __syncthreads();
    if (tid == 0) {
        float S = 0.f;
        for (int i = 0; i < 8; i++) S += sRs[i];
        int pi = b * 8 + t;
        g_lm[pi] = M; g_li[pi] = sI; g_ls[pi] = S;
    }
}

// ---------------- kE: per-batch combine -> outputs ----------------
__global__ void kE(float* __restrict__ out, int out_size) {
    int tid = threadIdx.x, b = tid >> 5, lane = tid & 31;
    __shared__ float sS[8];
    __shared__ int   sOp[8];
    float m = -INFINITY, s = 0.f; int ix = INT_MAX;
    if (lane < 8) { m = g_lm[b * 8 + lane]; s = g_ls[b * 8 + lane]; ix = g_li[b * 8 + lane]; }
    float M = m; int I = ix;
    #pragma unroll
    for (int o = 16; o; o >>= 1) {
        float om = __shfl_xor_sync(0xffffffffu, M, o);
        int   oi = __shfl_xor_sync(0xffffffffu, I, o);
        if (om > M || (om == M && oi < I)) { M = om; I = oi; }
    }
    float term = (m == -INFINITY) ? 0.f : s * __expf(m - M);
    float S = warpSum(term);
    if (lane == 0) { sS[b] = S; sOp[b] = I; }
    __syncthreads();
    if (tid < 8) {
        int op = sOp[tid];
        float Sb = sS[tid];
        if (tid < out_size)      out[tid]      = (float)(op / Nv);
        if (8 + tid < out_size)  out[8 + tid]  = (float)(op % Nv);
        if (16 + tid < out_size) out[16 + tid] = -logf(Sb);
    }
    if (tid == 0 && out_size > 24) {
        float ent = 0.f;
        for (int i = 0; i < 8; i++) ent += logf(sS[i]) / sS[i];
        out[24] = ent;
    }
}

// ---------------- launch ----------------
extern "C" void kernel_launch(void* const* d_in, const int* in_sizes, int n_in,
                              void* d_out, int out_size) {
    (void)in_sizes; (void)n_in;
    const float* fixedc = (const float*)d_in[1];
    const float* prev   = (const float*)d_in[2];
    const float* ndf    = (const float*)d_in[3];
    const float* veh    = (const float*)d_in[4];
    const float* gVs    = (const float*)d_in[5];
    const float* gKs    = (const float*)d_in[6];
    const float* lKs    = (const float*)d_in[7];
    const void*  mask   = d_in[8];
    const float* pcs    = (const float*)d_in[9];
    const float* W1     = (const float*)d_in[10];
    const float* W2     = (const float*)d_in[11];
    const float* po     = (const float*)d_in[12];

    kA<<<D3 + 1 + 64, 256>>>(W1, W2, mask, fixedc, prev, veh, pcs);
    kB<<<dim3(8, Vv, Bv), 256>>>(gKs, gVs, ndf, mask);
    kC<<<64, 256>>>(po);
    kD<<<dim3(8, Bv), 256>>>(lKs, ndf, mask);
    kE<<<1, 256>>>((float*)d_out, out_size);
}

// round 7
// speedup vs baseline: 2.6536x; 1.9914x over previous
#include <cuda_runtime.h>
#include <math.h>
#include <limits.h>

// Problem constants
#define Bv 8
#define Vv 8
#define Nv 1000
#define Dv 256
#define Hv 8
#define KSv 32
#define D3 768
#define SCALE_K 0.17677669529663687f   // 1/sqrt(32)
#define SCALE_D 0.0625f                // 1/sqrt(256)

// ---------------- scratch ----------------
__device__ float g_A8[D3 * 8];      // nde row j = A8[j][0..6]@feats + A8[j][7]*flag
__device__ int   g_mask_mode;       // 0=uint8/bool, 1=int32, 2=float32
__device__ float g_query[64 * Dv];
__device__ float g_fQ[64 * Dv];     // pre-scaled by 1/16
__device__ float g_am[4096];        // ((h*8+b)*8+v)*8 + t
__device__ float g_as[4096];
__device__ float g_aacc[4096 * 32];
__device__ float g_lm[256];         // b*32 + t
__device__ float g_ls[256];
__device__ int   g_li[256];
__device__ unsigned int g_cnt;      // kD completion counter (reset by kA each launch)

__device__ __forceinline__ bool mask_at(const void* m, int mode, int idx) {
    if (mode == 0) return ((const unsigned char*)m)[idx] != 0;
    if (mode == 1) return ((const int*)m)[idx] != 0;
    return ((const float*)m)[idx] != 0.0f;
}
__device__ __forceinline__ float warpMax(float v) {
    #pragma unroll
    for (int o = 16; o; o >>= 1) v = fmaxf(v, __shfl_xor_sync(0xffffffffu, v, o));
    return v;
}
__device__ __forceinline__ float warpSum(float v) {
    #pragma unroll
    for (int o = 16; o; o >>= 1) v += __shfl_xor_sync(0xffffffffu, v, o);
    return v;
}

// ---------------- kA: A8 build (0..767), sniff+counter reset (768), query (769..832) -----
__global__ void kA(const float* __restrict__ W1, const float* __restrict__ W2,
                   const void* __restrict__ mask, const float* __restrict__ fixedc,
                   const float* __restrict__ prev, const float* __restrict__ veh,
                   const float* __restrict__ pcs) {
    int j = blockIdx.x;
    int tid = threadIdx.x;
    if (j < D3) {
        float p[7] = {0, 0, 0, 0, 0, 0, 0};
        const float* w2row = W2 + (size_t)j * 769;
        for (int k = tid; k < D3; k += 256) {
            float w2 = w2row[k];
            const float* w1r = W1 + k * 7;
            #pragma unroll
            for (int i = 0; i < 7; i++) p[i] += w2 * w1r[i];
        }
        #pragma unroll
        for (int i = 0; i < 7; i++) p[i] = warpSum(p[i]);
        __shared__ float red[8][7];
        if ((tid & 31) == 0)
            #pragma unroll
            for (int i = 0; i < 7; i++) red[tid >> 5][i] = p[i];
        __syncthreads();
        if (tid < 7) {
            float s = 0.f;
            #pragma unroll
            for (int w = 0; w < 8; w++) s += red[w][tid];
            g_A8[j * 8 + tid] = W1[j * 7 + tid] + s;
        } else if (tid == 7) {
            g_A8[j * 8 + 7] = w2row[768];
        }
    } else if (j == D3) {
        if (tid == 0) {
            const unsigned int* w = (const unsigned int*)mask;
            bool allF = true, allI = true;
            for (int i = 0; i < 16; i++) {
                unsigned int x = w[i];
                if (x != 0x3F800000u && x != 0u) allF = false;
                if (x > 1u) allI = false;
            }
            g_mask_mode = allF ? 2 : (allI ? 1 : 0);
            g_cnt = 0;                      // reset kD completion counter each replay
        }
    } else {
        int bv = j - (D3 + 1);
        __shared__ __align__(16) float scv[264];
        scv[tid] = prev[(size_t)bv * Dv + tid];
        if (tid < 8) scv[256 + tid] = veh[bv * 8 + tid];
        __syncthreads();
        const float4* wr = (const float4*)(pcs + (size_t)tid * 264);
        const float4* sc4 = (const float4*)scv;
        float dot = 0.f;
        #pragma unroll 6
        for (int jj = 0; jj < 66; jj++) {
            float4 w4 = wr[jj], s4 = sc4[jj];
            dot += w4.x * s4.x + w4.y * s4.y + w4.z * s4.z + w4.w * s4.w;
        }
        g_query[(size_t)bv * Dv + tid] = fixedc[(bv >> 3) * Dv + tid] + dot;
    }
}

// ---------------- kB: attention partials. block=(t,b,h), warp=v, K/V staged in smem ------
__global__ void __launch_bounds__(256) kB(const float* __restrict__ gKs,
                                          const float* __restrict__ gVs,
                                          const float* __restrict__ ndf,
                                          const void* __restrict__ mask) {
    int t = blockIdx.x, b = blockIdx.y, h = blockIdx.z;
    int tid = threadIdx.x, v = tid >> 5, lane = tid & 31;
    // sK/sV: 128 rows, stride 36 floats (bank-optimal for lane=row float4 reads)
    __shared__ __align__(16) float smem[9472];   // sK[4608] | sV[4608] | sq[256]
    float* sK = smem;
    float* sV = smem + 4608;
    float* sq = smem + 9216;

    sq[tid] = g_query[((size_t)(b * Vv + v)) * Dv + h * 32 + lane] * SCALE_K;

    size_t base = ((size_t)(h * Bv + b)) * Nv * KSv;
    const float4* K4 = (const float4*)(gKs + base);
    const float4* V4 = (const float4*)(gVs + base);
    for (int i = tid; i < 1024; i += 256) {
        int row = i >> 3, c4 = i & 7;
        int n = t * 128 + row;
        float4 kv = make_float4(0, 0, 0, 0), vv = kv;
        if (n < Nv) { kv = K4[n * 8 + c4]; vv = V4[n * 8 + c4]; }
        *(float4*)&sK[row * 36 + c4 * 4] = kv;
        *(float4*)&sV[row * 36 + c4 * 4] = vv;
    }

    // qa = (scaled q_v)ᵀ A8K  (once per warp; A8 reads L2/L1-resident)
    float qa[8];
    {
        float qk = sq[tid];   // own value, written by this thread
        const float4* ar = (const float4*)(g_A8 + (256 + h * 32 + lane) * 8);
        float4 a0 = ar[0], a1 = ar[1];
        float av[8] = {a0.x, a0.y, a0.z, a0.w, a1.x, a1.y, a1.z, a1.w};
        #pragma unroll
        for (int jj = 0; jj < 8; jj++) qa[jj] = warpSum(qk * av[jj]);
    }
    __syncthreads();

    int mode = g_mask_mode;
    int mbase = (b * Vv + v) * Nv;
    const float* sqv = sq + v * 32;

    float m = -INFINITY, s = 0.f;
    float fw[8];
    float acc[32];
    #pragma unroll
    for (int jj = 0; jj < 8; jj++) fw[jj] = 0.f;
    #pragma unroll
    for (int k = 0; k < 32; k++) acc[k] = 0.f;

    #pragma unroll
    for (int it = 0; it < 4; it++) {
        int nl = it * 32 + lane;
        int n = t * 128 + nl;
        bool ok = (n < Nv) && mask_at(mask, mode, mbase + n);
        if (ok) {
            const float4* fp = (const float4*)(ndf + (size_t)(mbase + n) * 8);
            float4 fA = fp[0], fB = fp[1];
            const float* kr = &sK[nl * 36];
            float d0 = 0, d1 = 0, d2 = 0, d3 = 0;
            #pragma unroll
            for (int c4 = 0; c4 < 8; c4++) {
                float4 kk = *(const float4*)&kr[c4 * 4];
                d0 += sqv[c4 * 4 + 0] * kk.x;
                d1 += sqv[c4 * 4 + 1] * kk.y;
                d2 += sqv[c4 * 4 + 2] * kk.z;
                d3 += sqv[c4 * 4 + 3] * kk.w;
            }
            float c = (d0 + d1) + (d2 + d3)
                    + qa[0] * fA.x + qa[1] * fA.y + qa[2] * fA.z + qa[3] * fA.w
                    + qa[4] * fB.x + qa[5] * fB.y + qa[6] * fB.z + qa[7] * fB.w;
            float mn = fmaxf(m, c);
            float fac = __expf(m - mn);
            float w = __expf(c - mn);
            m = mn;
            s = s * fac + w;
            const float* vr = &sV[nl * 36];
            #pragma unroll
            for (int c4 = 0; c4 < 8; c4++) {
                float4 vv = *(const float4*)&vr[c4 * 4];
                acc[c4 * 4 + 0] = acc[c4 * 4 + 0] * fac + w * vv.x;
                acc[c4 * 4 + 1] = acc[c4 * 4 + 1] * fac + w * vv.y;
                acc[c4 * 4 + 2] = acc[c4 * 4 + 2] * fac + w * vv.z;
                acc[c4 * 4 + 3] = acc[c4 * 4 + 3] * fac + w * vv.w;
            }
            fw[0] = fw[0] * fac + w * fA.x; fw[1] = fw[1] * fac + w * fA.y;
            fw[2] = fw[2] * fac + w * fA.z; fw[3] = fw[3] * fac + w * fA.w;
            fw[4] = fw[4] * fac + w * fB.x; fw[5] = fw[5] * fac + w * fB.y;
            fw[6] = fw[6] * fac + w * fB.z; fw[7] = fw[7] * fac + w * fB.w;
        }
    }

    float Mw = warpMax(m);
    float sc = (m == -INFINITY) ? 0.f : __expf(m - Mw);
    float Sw = warpSum(s * sc);
    float fwt[8];
    #pragma unroll
    for (int jj = 0; jj < 8; jj++) fwt[jj] = warpSum(fw[jj] * sc);

    __syncthreads();   // sK/sV/sq dead; reuse smem as per-warp transpose scratch
    float* sw = smem + v * 1024;
    #pragma unroll
    for (int k = 0; k < 32; k++) sw[k * 32 + ((lane + k) & 31)] = acc[k] * sc;
    __syncwarp();
    float col = 0.f;
    #pragma unroll
    for (int l = 0; l < 32; l++) col += sw[lane * 32 + ((l + lane) & 31)];
    {   // V-side dynamic correction: + A8V[h*32+lane][:] . fwt
        const float4* avr = (const float4*)(g_A8 + (h * 32 + lane) * 8);
        float4 a0 = avr[0], a1 = avr[1];
        col += a0.x * fwt[0] + a0.y * fwt[1] + a0.z * fwt[2] + a0.w * fwt[3]
             + a1.x * fwt[4] + a1.y * fwt[5] + a1.z * fwt[6] + a1.w * fwt[7];
    }

    int p = ((h * Bv + b) * Vv + v) * 8 + t;
    if (lane == 0) { g_am[p] = Mw; g_as[p] = Sw; }
    g_aacc[p * 32 + lane] = col;
}

// ---------------- kC: combine + final_Q (block per (b,v), warp per head) ----------
__global__ void kC(const float* __restrict__ po) {
    int bv = blockIdx.x;
    int b = bv >> 3, v = bv & 7;
    int tid = threadIdx.x, h = tid >> 5, lane = tid & 31;
    __shared__ __align__(16) float sC[256];
    int base = (h * Bv + b) * 64;
    float m1 = g_am[base + lane], m2 = g_am[base + 32 + lane];
    float M = warpMax(fmaxf(m1, m2));
    float ss = g_as[base + lane] * __expf(m1 - M) + g_as[base + 32 + lane] * __expf(m2 - M);
    float S = warpSum(ss);
    float invS = 1.f / S;
    float sum = 0.f;
    #pragma unroll
    for (int tt = 0; tt < 8; tt++) {
        int pp = base + v * 8 + tt;
        float mt = g_am[pp];
        sum += g_aacc[pp * 32 + lane] * __expf(mt - M);
    }
    sC[h * 32 + lane] = sum * invS;
    __syncthreads();
    const float4* wr = (const float4*)(po + (size_t)tid * Dv);
    const float4* sc4 = (const float4*)sC;
    float dot = 0.f;
    #pragma unroll 8
    for (int jj = 0; jj < 64; jj++) {
        float4 w4 = wr[jj], s4 = sc4[jj];
        dot += w4.x * s4.x + w4.y * s4.y + w4.z * s4.z + w4.w * s4.w;
    }
    g_fQ[(size_t)bv * Dv + tid] = dot * SCALE_D;   // pre-scaled for logits
}

// ---------------- kD: logits. block=(tile32,b); 8 threads/node; last block finalizes -----
__global__ void __launch_bounds__(256) kD(const float* __restrict__ lKs,
                                          const float* __restrict__ ndf,
                                          const void* __restrict__ mask,
                                          float* __restrict__ out, int out_size) {
    int t = blockIdx.x, b = blockIdx.y;
    int tid = threadIdx.x, w = tid >> 5, lane = tid & 31;
    // sFQ: v stride 288 words, 32-dim chunk stride 36 (bank-shifted per chunk)
    __shared__ __align__(16) float sFQ[8 * 288];
    __shared__ float sQA[64];
    __shared__ float sRm[8]; __shared__ int sRi[8]; __shared__ float sRs[8];
    __shared__ float sM; __shared__ int sI; __shared__ int sLast;

    for (int i = tid; i < 2048; i += 256) {
        int vv = i >> 8, c = i & 255;
        sFQ[vv * 288 + (c >> 5) * 36 + (c & 31)] = g_fQ[((size_t)(b * Vv + vv)) * Dv + c];
    }
    {   // qa3_v = (scaled fQ_v)ᵀ A8_lK, warp w handles v=w
        float p8[8] = {0, 0, 0, 0, 0, 0, 0, 0};
        for (int c = lane; c < 256; c += 32) {
            float fq = g_fQ[((size_t)(b * Vv + w)) * Dv + c];
            const float4* ar = (const float4*)(g_A8 + (512 + c) * 8);
            float4 a0 = ar[0], a1 = ar[1];
            p8[0] += fq * a0.x; p8[1] += fq * a0.y; p8[2] += fq * a0.z; p8[3] += fq * a0.w;
            p8[4] += fq * a1.x; p8[5] += fq * a1.y; p8[6] += fq * a1.z; p8[7] += fq * a1.w;
        }
        #pragma unroll
        for (int jj = 0; jj < 8; jj++) p8[jj] = warpSum(p8[jj]);
        if (lane < 8) sQA[w * 8 + lane] = p8[lane];
    }
    __syncthreads();

    int nd = lane >> 3, ch = lane & 7;          // 4 nodes/warp, 8 dim-chunks/node
    int n = t * 32 + w * 4 + nd;
    bool valid = n < Nv;
    float dv[8] = {0, 0, 0, 0, 0, 0, 0, 0};
    if (valid) {
        const float4* kp = (const float4*)(lKs + ((size_t)b * Nv + n) * Dv) + ch * 8;
        float4 kk[8];
        #pragma unroll
        for (int c4 = 0; c4 < 8; c4++) kk[c4] = kp[c4];     // front-batched, MLP=8
        #pragma unroll
        for (int c4 = 0; c4 < 8; c4++) {
            #pragma unroll
            for (int vv = 0; vv < 8; vv++) {
                float4 fq = *(const float4*)&sFQ[vv * 288 + ch * 36 + c4 * 4];
                dv[vv] += fq.x * kk[c4].x + fq.y * kk[c4].y + fq.z * kk[c4].z + fq.w * kk[c4].w;
            }
        }
    }
    #pragma unroll
    for (int o = 1; o < 8; o <<= 1)
        #pragma unroll
        for (int vv = 0; vv < 8; vv++) dv[vv] += __shfl_xor_sync(0xffffffffu, dv[vv], o);

    int mode = g_mask_mode;
    float vals[8];
    float best = -INFINITY; int bidx = INT_MAX;
    if (ch == 0 && valid) {
        #pragma unroll
        for (int vv = 0; vv < 8; vv++) {
            float val = -INFINITY;
            int midx = (b * Vv + vv) * Nv + n;
            if (mask_at(mask, mode, midx)) {
                const float4* fp = (const float4*)(ndf + (size_t)midx * 8);
                float4 fA = fp[0], fB = fp[1];
                const float* qa = &sQA[vv * 8];
                float e = dv[vv]
                        + qa[0] * fA.x + qa[1] * fA.y + qa[2] * fA.z + qa[3] * fA.w
                        + qa[4] * fB.x + qa[5] * fB.y + qa[6] * fB.z + qa[7] * fB.w;
                val = tanhf(e) * 10.0f;
            }
            vals[vv] = val;
            if (val > best) { best = val; bidx = vv * Nv + n; }
        }
    } else {
        #pragma unroll
        for (int vv = 0; vv < 8; vv++) vals[vv] = -INFINITY;
    }
    #pragma unroll
    for (int o = 16; o; o >>= 1) {
        float om = __shfl_xor_sync(0xffffffffu, best, o);
        int   oi = __shfl_xor_sync(0xffffffffu, bidx, o);
        if (om > best || (om == best && oi < bidx)) { best = om; bidx = oi; }
    }
    if (lane == 0) { sRm[w] = best; sRi[w] = bidx; }
    __syncthreads();
    if (tid == 0) {
        float M = -INFINITY; int I = INT_MAX;
        for (int i = 0; i < 8; i++)
            if (sRm[i] > M || (sRm[i] == M && sRi[i] < I)) { M = sRm[i]; I = sRi[i]; }
        sM = M; sI = I;
    }
    __syncthreads();
    float M = sM;
    float es = 0.f;
    if (ch == 0 && valid) {
        #pragma unroll
        for (int vv = 0; vv < 8; vv++)
            if (vals[vv] != -INFINITY) es += __expf(vals[vv] - M);
    }
    es = warpSum(es);
    if (lane == 0) sRs[w] = es;
    __syncthreads();
    if (tid == 0) {
        float S = 0.f;
        for (int i = 0; i < 8; i++) S += sRs[i];
        int pi = b * 32 + t;
        g_lm[pi] = M; g_li[pi] = sI; g_ls[pi] = S;
        __threadfence();
        unsigned int old = atomicAdd(&g_cnt, 1u);
        sLast = (old == 255u) ? 1 : 0;
    }
    __syncthreads();
    if (!sLast) return;
    __threadfence();   // acquire: make all blocks' partials visible

    // ---- final combine (ex-kE): warp w = batch, lane = partial tile ----
    float m2 = g_lm[w * 32 + lane];
    float s2 = g_ls[w * 32 + lane];
    int   ix = g_li[w * 32 + lane];
    float M2 = m2; int I2 = ix;
    #pragma unroll
    for (int o = 16; o; o >>= 1) {
        float om = __shfl_xor_sync(0xffffffffu, M2, o);
        int   oi = __shfl_xor_sync(0xffffffffu, I2, o);
        if (om > M2 || (om == M2 && oi < I2)) { M2 = om; I2 = oi; }
    }
    float term = (m2 == -INFINITY) ? 0.f : s2 * __expf(m2 - M2);
    float S2 = warpSum(term);
    if (lane == 0) { sRs[w] = S2; sRi[w] = I2; }
    __syncthreads();
    if (tid < 8) {
        int op = sRi[tid];
        float Sb = sRs[tid];
        if (tid < out_size)      out[tid]      = (float)(op / Nv);
        if (8 + tid < out_size)  out[8 + tid]  = (float)(op % Nv);
        if (16 + tid < out_size) out[16 + tid] = -logf(Sb);
    }
    if (tid == 0 && out_size > 24) {
        float ent = 0.f;
        for (int i = 0; i < 8; i++) ent += logf(sRs[i]) / sRs[i];
        out[24] = ent;
    }
}

// ---------------- launch ----------------
extern "C" void kernel_launch(void* const* d_in, const int* in_sizes, int n_in,
                              void* d_out, int out_size) {
    (void)in_sizes; (void)n_in;
    const float* fixedc = (const float*)d_in[1];
    const float* prev   = (const float*)d_in[2];
    const float* ndf    = (const float*)d_in[3];
    const float* veh    = (const float*)d_in[4];
    const float* gVs    = (const float*)d_in[5];
    const float* gKs    = (const float*)d_in[6];
    const float* lKs    = (const float*)d_in[7];
    const void*  mask   = d_in[8];
    const float* pcs    = (const float*)d_in[9];
    const float* W1     = (const float*)d_in[10];
    const float* W2     = (const float*)d_in[11];
    const float* po     = (const float*)d_in[12];

    kA<<<D3 + 1 + 64, 256>>>(W1, W2, mask, fixedc, prev, veh, pcs);
    kB<<<dim3(8, Bv, Hv), 256>>>(gKs, gVs, ndf, mask);
    kC<<<64, 256>>>(po);
    kD<<<dim3(32, Bv), 256>>>(lKs, ndf, mask, (float*)d_out, out_size);
}

// round 12
// speedup vs baseline: 2.8557x; 1.0762x over previous
#include <cuda_runtime.h>
#include <math.h>
#include <limits.h>

// Problem constants
#define Bv 8
#define Vv 8
#define Nv 1000
#define Dv 256
#define Hv 8
#define KSv 32
#define D3 768
#define SCALE_K 0.17677669529663687f   // 1/sqrt(32)
#define SCALE_D 0.0625f                // 1/sqrt(256)
#define NTB 16                         // kB tiles (64 nodes each)
#define NTD 63                         // kD tiles (16 nodes each)

// ---------------- scratch ----------------
__device__ float g_A8[D3 * 8];      // nde row j = A8[j][0..6]@feats + A8[j][7]*flag
__device__ int   g_mask_mode;       // 0=uint8/bool, 1=int32, 2=float32
__device__ float g_query[64 * Dv];
__device__ float g_fQ[64 * Dv];     // pre-scaled by 1/16
__device__ float g_QA[64 * 8];      // qa3 per (b,v): (scaled fQ_v)' A8_lK
__device__ float g_am[8192];        // ((h*8+b)*8+v)*16 + t
__device__ float g_as[8192];
__device__ float g_aacc[8192 * 32];
__device__ float g_lm[512];         // b*64 + t  (t < 63 used)
__device__ float g_ls[512];
__device__ int   g_li[512];
__device__ unsigned int g_cnt;      // kD completion counter (reset by kA each launch)

__device__ __forceinline__ bool mask_at(const void* m, int mode, int idx) {
    if (mode == 0) return ((const unsigned char*)m)[idx] != 0;
    if (mode == 1) return ((const int*)m)[idx] != 0;
    return ((const float*)m)[idx] != 0.0f;
}
__device__ __forceinline__ float warpMax(float v) {
    #pragma unroll
    for (int o = 16; o; o >>= 1) v = fmaxf(v, __shfl_xor_sync(0xffffffffu, v, o));
    return v;
}
__device__ __forceinline__ float warpSum(float v) {
    #pragma unroll
    for (int o = 16; o; o >>= 1) v += __shfl_xor_sync(0xffffffffu, v, o);
    return v;
}

// ---------------- kA: A8 build (0..767), sniff+counter reset (768), query (769..832) -----
__global__ void kA(const float* __restrict__ W1, const float* __restrict__ W2,
                   const void* __restrict__ mask, const float* __restrict__ fixedc,
                   const float* __restrict__ prev, const float* __restrict__ veh,
                   const float* __restrict__ pcs) {
    int j = blockIdx.x;
    int tid = threadIdx.x;
    if (j < D3) {
        float p[7] = {0, 0, 0, 0, 0, 0, 0};
        const float* w2row = W2 + (size_t)j * 769;
        for (int k = tid; k < D3; k += 256) {
            float w2 = w2row[k];
            const float* w1r = W1 + k * 7;
            #pragma unroll
            for (int i = 0; i < 7; i++) p[i] += w2 * w1r[i];
        }
        #pragma unroll
        for (int i = 0; i < 7; i++) p[i] = warpSum(p[i]);
        __shared__ float red[8][7];
        if ((tid & 31) == 0)
            #pragma unroll
            for (int i = 0; i < 7; i++) red[tid >> 5][i] = p[i];
        __syncthreads();
        if (tid < 7) {
            float s = 0.f;
            #pragma unroll
            for (int w = 0; w < 8; w++) s += red[w][tid];
            g_A8[j * 8 + tid] = W1[j * 7 + tid] + s;
        } else if (tid == 7) {
            g_A8[j * 8 + 7] = w2row[768];
        }
    } else if (j == D3) {
        if (tid == 0) {
            const unsigned int* w = (const unsigned int*)mask;
            bool allF = true, allI = true;
            for (int i = 0; i < 16; i++) {
                unsigned int x = w[i];
                if (x != 0x3F800000u && x != 0u) allF = false;
                if (x > 1u) allI = false;
            }
            g_mask_mode = allF ? 2 : (allI ? 1 : 0);
            g_cnt = 0;                      // reset kD completion counter each replay
        }
    } else {
        int bv = j - (D3 + 1);
        __shared__ __align__(16) float scv[264];
        scv[tid] = prev[(size_t)bv * Dv + tid];
        if (tid < 8) scv[256 + tid] = veh[bv * 8 + tid];
        __syncthreads();
        const float4* wr = (const float4*)(pcs + (size_t)tid * 264);
        const float4* sc4 = (const float4*)scv;
        float dot = 0.f;
        #pragma unroll 6
        for (int jj = 0; jj < 66; jj++) {
            float4 w4 = wr[jj], s4 = sc4[jj];
            dot += w4.x * s4.x + w4.y * s4.y + w4.z * s4.z + w4.w * s4.w;
        }
        g_query[(size_t)bv * Dv + tid] = fixedc[(bv >> 3) * Dv + tid] + dot;
    }
}

// ---------------- kB: attention partials. block=(t64,b,h), warp=v, K/V staged in smem ----
__global__ void __launch_bounds__(256) kB(const float* __restrict__ gKs,
                                          const float* __restrict__ gVs,
                                          const float* __restrict__ ndf,
                                          const void* __restrict__ mask) {
    int t = blockIdx.x, b = blockIdx.y, h = blockIdx.z;
    int tid = threadIdx.x, v = tid >> 5, lane = tid & 31;
    // sK/sV: 64 rows, stride 36 floats; transpose phase reuses [0, 8192)
    __shared__ __align__(16) float smem[8448];   // sK[2304] | sV[2304] | ... | sq @ 8192
    float* sK = smem;
    float* sV = smem + 2304;
    float* sq = smem + 8192;

    sq[tid] = g_query[((size_t)(b * Vv + v)) * Dv + h * 32 + lane] * SCALE_K;

    size_t base = ((size_t)(h * Bv + b)) * Nv * KSv;
    const float4* K4 = (const float4*)(gKs + base);
    const float4* V4 = (const float4*)(gVs + base);
    #pragma unroll
    for (int i = tid; i < 512; i += 256) {
        int row = i >> 3, c4 = i & 7;
        int n = t * 64 + row;
        float4 kv = make_float4(0, 0, 0, 0), vv = kv;
        if (n < Nv) { kv = K4[n * 8 + c4]; vv = V4[n * 8 + c4]; }
        *(float4*)&sK[row * 36 + c4 * 4] = kv;
        *(float4*)&sV[row * 36 + c4 * 4] = vv;
    }

    // qa = (scaled q_v)' A8K  (once per warp)
    float qa[8];
    {
        float qk = sq[tid];   // own value, written by this thread
        const float4* ar = (const float4*)(g_A8 + (256 + h * 32 + lane) * 8);
        float4 a0 = ar[0], a1 = ar[1];
        float av[8] = {a0.x, a0.y, a0.z, a0.w, a1.x, a1.y, a1.z, a1.w};
        #pragma unroll
        for (int jj = 0; jj < 8; jj++) qa[jj] = warpSum(qk * av[jj]);
    }
    __syncthreads();

    int mode = g_mask_mode;
    int mbase = (b * Vv + v) * Nv;
    const float* sqv = sq + v * 32;

    float m = -INFINITY, s = 0.f;
    float fw[8];
    float acc[32];
    #pragma unroll
    for (int jj = 0; jj < 8; jj++) fw[jj] = 0.f;
    #pragma unroll
    for (int k = 0; k < 32; k++) acc[k] = 0.f;

    #pragma unroll
    for (int it = 0; it < 2; it++) {
        int nl = it * 32 + lane;
        int n = t * 64 + nl;
        bool ok = (n < Nv) && mask_at(mask, mode, mbase + n);
        if (ok) {
            const float4* fp = (const float4*)(ndf + (size_t)(mbase + n) * 8);
            float4 fA = fp[0], fB = fp[1];
            const float* kr = &sK[nl * 36];
            float d0 = 0, d1 = 0, d2 = 0, d3 = 0;
            #pragma unroll
            for (int c4 = 0; c4 < 8; c4++) {
                float4 kk = *(const float4*)&kr[c4 * 4];
                d0 += sqv[c4 * 4 + 0] * kk.x;
                d1 += sqv[c4 * 4 + 1] * kk.y;
                d2 += sqv[c4 * 4 + 2] * kk.z;
                d3 += sqv[c4 * 4 + 3] * kk.w;
            }
            float c = (d0 + d1) + (d2 + d3)
                    + qa[0] * fA.x + qa[1] * fA.y + qa[2] * fA.z + qa[3] * fA.w
                    + qa[4] * fB.x + qa[5] * fB.y + qa[6] * fB.z + qa[7] * fB.w;
            float mn = fmaxf(m, c);
            float fac = __expf(m - mn);
            float w = __expf(c - mn);
            m = mn;
            s = s * fac + w;
            const float* vr = &sV[nl * 36];
            #pragma unroll
            for (int c4 = 0; c4 < 8; c4++) {
                float4 vv = *(const float4*)&vr[c4 * 4];
                acc[c4 * 4 + 0] = acc[c4 * 4 + 0] * fac + w * vv.x;
                acc[c4 * 4 + 1] = acc[c4 * 4 + 1] * fac + w * vv.y;
                acc[c4 * 4 + 2] = acc[c4 * 4 + 2] * fac + w * vv.z;
                acc[c4 * 4 + 3] = acc[c4 * 4 + 3] * fac + w * vv.w;
            }
            fw[0] = fw[0] * fac + w * fA.x; fw[1] = fw[1] * fac + w * fA.y;
            fw[2] = fw[2] * fac + w * fA.z; fw[3] = fw[3] * fac + w * fA.w;
            fw[4] = fw[4] * fac + w * fB.x; fw[5] = fw[5] * fac + w * fB.y;
            fw[6] = fw[6] * fac + w * fB.z; fw[7] = fw[7] * fac + w * fB.w;
        }
    }

    float Mw = warpMax(m);
    float sc = (m == -INFINITY) ? 0.f : __expf(m - Mw);
    float Sw = warpSum(s * sc);
    float fwt[8];
    #pragma unroll
    for (int jj = 0; jj < 8; jj++) fwt[jj] = warpSum(fw[jj] * sc);

    __syncthreads();   // sK/sV dead; reuse smem as per-warp transpose scratch
    float* sw = smem + v * 1024;
    #pragma unroll
    for (int k = 0; k < 32; k++) sw[k * 32 + ((lane + k) & 31)] = acc[k] * sc;
    __syncwarp();
    float col = 0.f;
    #pragma unroll
    for (int l = 0; l < 32; l++) col += sw[lane * 32 + ((l + lane) & 31)];
    {   // V-side dynamic correction: + A8V[h*32+lane][:] . fwt
        const float4* avr = (const float4*)(g_A8 + (h * 32 + lane) * 8);
        float4 a0 = avr[0], a1 = avr[1];
        col += a0.x * fwt[0] + a0.y * fwt[1] + a0.z * fwt[2] + a0.w * fwt[3]
             + a1.x * fwt[4] + a1.y * fwt[5] + a1.z * fwt[6] + a1.w * fwt[7];
    }

    int p = ((h * Bv + b) * Vv + v) * NTB + t;
    if (lane == 0) { g_am[p] = Mw; g_as[p] = Sw; }
    g_aacc[p * 32 + lane] = col;
}

// ---------------- kC: combine + final_Q + qa3 (block per (b,v), warp per head) -----------
__global__ void kC(const float* __restrict__ po) {
    int bv = blockIdx.x;
    int b = bv >> 3, v = bv & 7;
    int tid = threadIdx.x, h = tid >> 5, lane = tid & 31;
    __shared__ __align__(16) float sC[256];
    __shared__ float red8[8][8];
    int base = (h * Bv + b) * (Vv * NTB);     // 128 partials per (h,b)
    float m1 = g_am[base + lane], m2 = g_am[base + 32 + lane];
    float m3 = g_am[base + 64 + lane], m4 = g_am[base + 96 + lane];
    float M = warpMax(fmaxf(fmaxf(m1, m2), fmaxf(m3, m4)));
    float ss = g_as[base + lane] * __expf(m1 - M) + g_as[base + 32 + lane] * __expf(m2 - M)
             + g_as[base + 64 + lane] * __expf(m3 - M) + g_as[base + 96 + lane] * __expf(m4 - M);
    float S = warpSum(ss);
    float invS = 1.f / S;
    float sum = 0.f;
    #pragma unroll
    for (int tt = 0; tt < NTB; tt++) {
        int pp = base + v * NTB + tt;
        float mt = g_am[pp];
        sum += g_aacc[pp * 32 + lane] * __expf(mt - M);
    }
    sC[h * 32 + lane] = sum * invS;
    __syncthreads();
    const float4* wr = (const float4*)(po + (size_t)tid * Dv);
    const float4* sc4 = (const float4*)sC;
    float dot = 0.f;
    #pragma unroll 8
    for (int jj = 0; jj < 64; jj++) {
        float4 w4 = wr[jj], s4 = sc4[jj];
        dot += w4.x * s4.x + w4.y * s4.y + w4.z * s4.z + w4.w * s4.w;
    }
    float fqs = dot * SCALE_D;
    g_fQ[(size_t)bv * Dv + tid] = fqs;        // pre-scaled for logits

    // qa3 = (scaled fQ)' A8_lK  -> g_QA[bv*8 + j]
    const float4* ar = (const float4*)(g_A8 + (512 + tid) * 8);
    float4 a0 = ar[0], a1 = ar[1];
    float p8[8] = {fqs * a0.x, fqs * a0.y, fqs * a0.z, fqs * a0.w,
                   fqs * a1.x, fqs * a1.y, fqs * a1.z, fqs * a1.w};
    #pragma unroll
    for (int jj = 0; jj < 8; jj++) p8[jj] = warpSum(p8[jj]);
    if (lane < 8) red8[h][lane] = p8[lane];
    __syncthreads();
    if (tid < 8) {
        float s8 = 0.f;
        #pragma unroll
        for (int w = 0; w < 8; w++) s8 += red8[w][tid];
        g_QA[bv * 8 + tid] = s8;
    }
}

// ---------------- kD: logits. block=(tile16,b); 16 thr/node; last block finalizes --------
__global__ void __launch_bounds__(256) kD(const float* __restrict__ lKs,
                                          const float* __restrict__ ndf,
                                          const void* __restrict__ mask,
                                          float* __restrict__ out, int out_size) {
    int t = blockIdx.x, b = blockIdx.y;
    int tid = threadIdx.x, w = tid >> 5, lane = tid & 31;
    int nd = lane >> 4, ch = lane & 15;       // 2 nodes/warp, 16 dim-chunks (16 floats) each
    // sFQ: v stride 320, chunk stride 20 (phase-conflict-free for 16-addr LDS.128)
    __shared__ __align__(16) float sFQ[8 * 320];
    __shared__ float sQA[64];
    __shared__ float sRm[8]; __shared__ int sRi[8]; __shared__ float sRs[8];
    __shared__ float sM; __shared__ int sI; __shared__ int sLast;

    for (int i = tid; i < 2048; i += 256) {
        int vv = i >> 8, c = i & 255;
        sFQ[vv * 320 + (c >> 4) * 20 + (c & 15)] = g_fQ[((size_t)(b * Vv + vv)) * Dv + c];
    }
    if (tid < 64) sQA[tid] = g_QA[b * 64 + tid];
    __syncthreads();

    int n = t * 16 + w * 2 + nd;
    bool valid = n < Nv;
    float dv[8] = {0, 0, 0, 0, 0, 0, 0, 0};
    if (valid) {
        const float4* kp = (const float4*)(lKs + ((size_t)b * Nv + n) * Dv) + ch * 4;
        float4 kk[4];
        #pragma unroll
        for (int c4 = 0; c4 < 4; c4++) kk[c4] = kp[c4];     // front-batched
        #pragma unroll
        for (int c4 = 0; c4 < 4; c4++) {
            #pragma unroll
            for (int vv = 0; vv < 8; vv++) {
                float4 fq = *(const float4*)&sFQ[vv * 320 + ch * 20 + c4 * 4];
                dv[vv] += fq.x * kk[c4].x + fq.y * kk[c4].y + fq.z * kk[c4].z + fq.w * kk[c4].w;
            }
        }
    }
    #pragma unroll
    for (int o = 1; o < 16; o <<= 1)
        #pragma unroll
        for (int vv = 0; vv < 8; vv++) dv[vv] += __shfl_xor_sync(0xffffffffu, dv[vv], o);

    // distributed masked tail: lane ch in [0,8) handles v = ch for its node
    int mode = g_mask_mode;
    float val = -INFINITY; int bidx = INT_MAX;
    if (valid && ch < 8) {
        int vv = ch;
        int midx = (b * Vv + vv) * Nv + n;
        if (mask_at(mask, mode, midx)) {
            const float4* fp = (const float4*)(ndf + (size_t)midx * 8);
            float4 fA = fp[0], fB = fp[1];
            const float* qa = &sQA[vv * 8];
            float e = dv[vv]
                    + qa[0] * fA.x + qa[1] * fA.y + qa[2] * fA.z + qa[3] * fA.w
                    + qa[4] * fB.x + qa[5] * fB.y + qa[6] * fB.z + qa[7] * fB.w;
            val = tanhf(e) * 10.0f;
            bidx = vv * Nv + n;
        }
    }
    float best = val; int bi = bidx;
    #pragma unroll
    for (int o = 16; o; o >>= 1) {
        float om = __shfl_xor_sync(0xffffffffu, best, o);
        int   oi = __shfl_xor_sync(0xffffffffu, bi, o);
        if (om > best || (om == best && oi < bi)) { best = om; bi = oi; }
    }
    if (lane == 0) { sRm[w] = best; sRi[w] = bi; }
    __syncthreads();
    if (tid == 0) {
        float M = -INFINITY; int I = INT_MAX;
        for (int i = 0; i < 8; i++)
            if (sRm[i] > M || (sRm[i] == M && sRi[i] < I)) { M = sRm[i]; I = sRi[i]; }
        sM = M; sI = I;
    }
    __syncthreads();
    float M = sM;
    float es = (val == -INFINITY) ? 0.f : __expf(val - M);
    es = warpSum(es);
    if (lane == 0) sRs[w] = es;
    __syncthreads();
    if (tid == 0) {
        float S = 0.f;
        for (int i = 0; i < 8; i++) S += sRs[i];
        int pi = b * 64 + t;
        g_lm[pi] = M; g_li[pi] = sI; g_ls[pi] = S;
        __threadfence();
        unsigned int old = atomicAdd(&g_cnt, 1u);
        sLast = (old == (NTD * Bv - 1)) ? 1 : 0;
    }
    __syncthreads();
    if (!sLast) return;
    __threadfence();   // acquire: make all blocks' partials visible

    // ---- final combine: warp w = batch; each lane folds partials lane and lane+32 ----
    // (NTD=63 > 32: the Round-8 bug was reading only lane<32 partials)
    float m2 = -INFINITY, s2 = 0.f; int ix = INT_MAX;
    if (lane < NTD) { m2 = g_lm[w * 64 + lane]; s2 = g_ls[w * 64 + lane]; ix = g_li[w * 64 + lane]; }
    {
        int i1 = lane + 32;
        if (i1 < NTD) {
            float mB = g_lm[w * 64 + i1];
            float sB = g_ls[w * 64 + i1];
            int   iB = g_li[w * 64 + i1];
            float Mn = fmaxf(m2, mB);
            float sN = ((m2 == -INFINITY) ? 0.f : s2 * __expf(m2 - Mn))
                     + ((mB == -INFINITY) ? 0.f : sB * __expf(mB - Mn));
            if (mB > m2 || (mB == m2 && iB < ix)) ix = iB;
            m2 = Mn; s2 = sN;
        }
    }
    float M2 = m2; int I2 = ix;
    #pragma unroll
    for (int o = 16; o; o >>= 1) {
        float om = __shfl_xor_sync(0xffffffffu, M2, o);
        int   oi = __shfl_xor_sync(0xffffffffu, I2, o);
        if (om > M2 || (om == M2 && oi < I2)) { M2 = om; I2 = oi; }
    }
    float term = (m2 == -INFINITY) ? 0.f : s2 * __expf(m2 - M2);
    float S2 = warpSum(term);
    if (lane == 0) { sRs[w] = S2; sRi[w] = I2; }
    __syncthreads();
    if (tid < 8) {
        int op = sRi[tid];
        float Sb = sRs[tid];
        if (tid < out_size)      out[tid]      = (float)(op / Nv);
        if (8 + tid < out_size)  out[8 + tid]  = (float)(op % Nv);
        if (16 + tid < out_size) out[16 + tid] = -logf(Sb);
    }
    if (tid == 0 && out_size > 24) {
        float ent = 0.f;
        for (int i = 0; i < 8; i++) ent += logf(sRs[i]) / sRs[i];
        out[24] = ent;
    }
}

// ---------------- launch ----------------
extern "C" void kernel_launch(void* const* d_in, const int* in_sizes, int n_in,
                              void* d_out, int out_size) {
    (void)in_sizes; (void)n_in;
    const float* fixedc = (const float*)d_in[1];
    const float* prev   = (const float*)d_in[2];
    const float* ndf    = (const float*)d_in[3];
    const float* veh    = (const float*)d_in[4];
    const float* gVs    = (const float*)d_in[5];
    const float* gKs    = (const float*)d_in[6];
    const float* lKs    = (const float*)d_in[7];
    const void*  mask   = d_in[8];
    const float* pcs    = (const float*)d_in[9];
    const float* W1     = (const float*)d_in[10];
    const float* W2     = (const float*)d_in[11];
    const float* po     = (const float*)d_in[12];

    kA<<<D3 + 1 + 64, 256>>>(W1, W2, mask, fixedc, prev, veh, pcs);
    kB<<<dim3(NTB, Bv, Hv), 256>>>(gKs, gVs, ndf, mask);
    kC<<<64, 256>>>(po);
    kD<<<dim3(NTD, Bv), 256>>>(lKs, ndf, mask, (float*)d_out, out_size);
}

// round 16
// speedup vs baseline: 2.9736x; 1.0413x over previous
#include <cuda_runtime.h>
#include <math.h>
#include <limits.h>

// Problem constants
#define Bv 8
#define Vv 8
#define Nv 1000
#define Dv 256
#define Hv 8
#define KSv 32
#define D3 768
#define SCALE_K 0.17677669529663687f   // 1/sqrt(32)
#define SCALE_D 0.0625f                // 1/sqrt(256)
#define NTB 16                         // kB tiles (64 nodes each)
#define NTD 125                        // kD tiles (8 nodes each, warp-per-node)

// ---------------- scratch ----------------
__device__ float g_A8[D3 * 8];      // nde row j = A8[j][0..6]@feats + A8[j][7]*flag
__device__ int   g_mask_mode;       // 0=uint8/bool, 1=int32, 2=float32
__device__ float g_query[64 * Dv];
__device__ float g_fQ[64 * Dv];     // pre-scaled by 1/16
__device__ float g_QAp[64 * 4 * 8]; // qa3 quarter-partials per (b,v): summed in kD staging
__device__ float g_am[8192];        // ((h*8+b)*8+v)*16 + t
__device__ float g_as[8192];
__device__ float g_aacc[8192 * 32];
__device__ float g_lm[1024];        // b*128 + t  (t < 125 used)
__device__ float g_ls[1024];
__device__ int   g_li[1024];
__device__ unsigned int g_cnt;      // kD completion counter (reset by kA each launch)

__device__ __forceinline__ bool mask_at(const void* m, int mode, int idx) {
    if (mode == 0) return ((const unsigned char*)m)[idx] != 0;
    if (mode == 1) return ((const int*)m)[idx] != 0;
    return ((const float*)m)[idx] != 0.0f;
}
__device__ __forceinline__ float warpMax(float v) {
    #pragma unroll
    for (int o = 16; o; o >>= 1) v = fmaxf(v, __shfl_xor_sync(0xffffffffu, v, o));
    return v;
}
__device__ __forceinline__ float warpSum(float v) {
    #pragma unroll
    for (int o = 16; o; o >>= 1) v += __shfl_xor_sync(0xffffffffu, v, o);
    return v;
}

// ---------------- kA: A8 build (0..767), sniff+counter reset (768), query (769..832) -----
__global__ void kA(const float* __restrict__ W1, const float* __restrict__ W2,
                   const void* __restrict__ mask, const float* __restrict__ fixedc,
                   const float* __restrict__ prev, const float* __restrict__ veh,
                   const float* __restrict__ pcs) {
    int j = blockIdx.x;
    int tid = threadIdx.x;
    if (j < D3) {
        float p[7] = {0, 0, 0, 0, 0, 0, 0};
        const float* w2row = W2 + (size_t)j * 769;
        for (int k = tid; k < D3; k += 256) {
            float w2 = w2row[k];
            const float* w1r = W1 + k * 7;
            #pragma unroll
            for (int i = 0; i < 7; i++) p[i] += w2 * w1r[i];
        }
        #pragma unroll
        for (int i = 0; i < 7; i++) p[i] = warpSum(p[i]);
        __shared__ float red[8][7];
        if ((tid & 31) == 0)
            #pragma unroll
            for (int i = 0; i < 7; i++) red[tid >> 5][i] = p[i];
        __syncthreads();
        if (tid < 7) {
            float s = 0.f;
            #pragma unroll
            for (int w = 0; w < 8; w++) s += red[w][tid];
            g_A8[j * 8 + tid] = W1[j * 7 + tid] + s;
        } else if (tid == 7) {
            g_A8[j * 8 + 7] = w2row[768];
        }
    } else if (j == D3) {
        if (tid == 0) {
            const unsigned int* w = (const unsigned int*)mask;
            bool allF = true, allI = true;
            for (int i = 0; i < 16; i++) {
                unsigned int x = w[i];
                if (x != 0x3F800000u && x != 0u) allF = false;
                if (x > 1u) allI = false;
            }
            g_mask_mode = allF ? 2 : (allI ? 1 : 0);
            g_cnt = 0;                      // reset kD completion counter each replay
        }
    } else {
        int bv = j - (D3 + 1);
        __shared__ __align__(16) float scv[264];
        scv[tid] = prev[(size_t)bv * Dv + tid];
        if (tid < 8) scv[256 + tid] = veh[bv * 8 + tid];
        __syncthreads();
        const float4* wr = (const float4*)(pcs + (size_t)tid * 264);
        const float4* sc4 = (const float4*)scv;
        float dot = 0.f;
        #pragma unroll 6
        for (int jj = 0; jj < 66; jj++) {
            float4 w4 = wr[jj], s4 = sc4[jj];
            dot += w4.x * s4.x + w4.y * s4.y + w4.z * s4.z + w4.w * s4.w;
        }
        g_query[(size_t)bv * Dv + tid] = fixedc[(bv >> 3) * Dv + tid] + dot;
    }
}

// ---------------- kB: attention partials. block=(t64,b,h), warp=v, K/V staged in smem ----
__global__ void __launch_bounds__(256) kB(const float* __restrict__ gKs,
                                          const float* __restrict__ gVs,
                                          const float* __restrict__ ndf,
                                          const void* __restrict__ mask) {
    int t = blockIdx.x, b = blockIdx.y, h = blockIdx.z;
    int tid = threadIdx.x, v = tid >> 5, lane = tid & 31;
    // sK/sV: 64 rows, stride 36 floats; transpose phase reuses [0, 8192)
    __shared__ __align__(16) float smem[8448];   // sK[2304] | sV[2304] | ... | sq @ 8192
    float* sK = smem;
    float* sV = smem + 2304;
    float* sq = smem + 8192;

    sq[tid] = g_query[((size_t)(b * Vv + v)) * Dv + h * 32 + lane] * SCALE_K;

    size_t base = ((size_t)(h * Bv + b)) * Nv * KSv;
    const float4* K4 = (const float4*)(gKs + base);
    const float4* V4 = (const float4*)(gVs + base);
    #pragma unroll
    for (int i = tid; i < 512; i += 256) {
        int row = i >> 3, c4 = i & 7;
        int n = t * 64 + row;
        float4 kv = make_float4(0, 0, 0, 0), vv = kv;
        if (n < Nv) { kv = K4[n * 8 + c4]; vv = V4[n * 8 + c4]; }
        *(float4*)&sK[row * 36 + c4 * 4] = kv;
        *(float4*)&sV[row * 36 + c4 * 4] = vv;
    }

    // qa = (scaled q_v)' A8K  (once per warp)
    float qa[8];
    {
        float qk = sq[tid];   // own value, written by this thread
        const float4* ar = (const float4*)(g_A8 + (256 + h * 32 + lane) * 8);
        float4 a0 = ar[0], a1 = ar[1];
        float av[8] = {a0.x, a0.y, a0.z, a0.w, a1.x, a1.y, a1.z, a1.w};
        #pragma unroll
        for (int jj = 0; jj < 8; jj++) qa[jj] = warpSum(qk * av[jj]);
    }
    __syncthreads();

    int mode = g_mask_mode;
    int mbase = (b * Vv + v) * Nv;
    const float* sqv = sq + v * 32;

    float m = -INFINITY, s = 0.f;
    float fw[8];
    float acc[32];
    #pragma unroll
    for (int jj = 0; jj < 8; jj++) fw[jj] = 0.f;
    #pragma unroll
    for (int k = 0; k < 32; k++) acc[k] = 0.f;

    #pragma unroll
    for (int it = 0; it < 2; it++) {
        int nl = it * 32 + lane;
        int n = t * 64 + nl;
        bool ok = (n < Nv) && mask_at(mask, mode, mbase + n);
        if (ok) {
            const float4* fp = (const float4*)(ndf + (size_t)(mbase + n) * 8);
            float4 fA = fp[0], fB = fp[1];
            const float* kr = &sK[nl * 36];
            float d0 = 0, d1 = 0, d2 = 0, d3 = 0;
            #pragma unroll
            for (int c4 = 0; c4 < 8; c4++) {
                float4 kk = *(const float4*)&kr[c4 * 4];
                d0 += sqv[c4 * 4 + 0] * kk.x;
                d1 += sqv[c4 * 4 + 1] * kk.y;
                d2 += sqv[c4 * 4 + 2] * kk.z;
                d3 += sqv[c4 * 4 + 3] * kk.w;
            }
            float c = (d0 + d1) + (d2 + d3)
                    + qa[0] * fA.x + qa[1] * fA.y + qa[2] * fA.z + qa[3] * fA.w
                    + qa[4] * fB.x + qa[5] * fB.y + qa[6] * fB.z + qa[7] * fB.w;
            float mn = fmaxf(m, c);
            float fac = __expf(m - mn);
            float w = __expf(c - mn);
            m = mn;
            s = s * fac + w;
            const float* vr = &sV[nl * 36];
            #pragma unroll
            for (int c4 = 0; c4 < 8; c4++) {
                float4 vv = *(const float4*)&vr[c4 * 4];
                acc[c4 * 4 + 0] = acc[c4 * 4 + 0] * fac + w * vv.x;
                acc[c4 * 4 + 1] = acc[c4 * 4 + 1] * fac + w * vv.y;
                acc[c4 * 4 + 2] = acc[c4 * 4 + 2] * fac + w * vv.z;
                acc[c4 * 4 + 3] = acc[c4 * 4 + 3] * fac + w * vv.w;
            }
            fw[0] = fw[0] * fac + w * fA.x; fw[1] = fw[1] * fac + w * fA.y;
            fw[2] = fw[2] * fac + w * fA.z; fw[3] = fw[3] * fac + w * fA.w;
            fw[4] = fw[4] * fac + w * fB.x; fw[5] = fw[5] * fac + w * fB.y;
            fw[6] = fw[6] * fac + w * fB.z; fw[7] = fw[7] * fac + w * fB.w;
        }
    }

    float Mw = warpMax(m);
    float sc = (m == -INFINITY) ? 0.f : __expf(m - Mw);
    float Sw = warpSum(s * sc);
    float fwt[8];
    #pragma unroll
    for (int jj = 0; jj < 8; jj++) fwt[jj] = warpSum(fw[jj] * sc);

    __syncthreads();   // sK/sV dead; reuse smem as per-warp transpose scratch
    float* sw = smem + v * 1024;
    #pragma unroll
    for (int k = 0; k < 32; k++) sw[k * 32 + ((lane + k) & 31)] = acc[k] * sc;
    __syncwarp();
    float col = 0.f;
    #pragma unroll
    for (int l = 0; l < 32; l++) col += sw[lane * 32 + ((l + lane) & 31)];
    {   // V-side dynamic correction: + A8V[h*32+lane][:] . fwt
        const float4* avr = (const float4*)(g_A8 + (h * 32 + lane) * 8);
        float4 a0 = avr[0], a1 = avr[1];
        col += a0.x * fwt[0] + a0.y * fwt[1] + a0.z * fwt[2] + a0.w * fwt[3]
             + a1.x * fwt[4] + a1.y * fwt[5] + a1.z * fwt[6] + a1.w * fwt[7];
    }

    int p = ((h * Bv + b) * Vv + v) * NTB + t;
    if (lane == 0) { g_am[p] = Mw; g_as[p] = Sw; }
    g_aacc[p * 32 + lane] = col;
}

// ---------------- kC: combine + final_Q + qa3 partials. block=(bv, quarter) --------------
__global__ void __launch_bounds__(256) kC(const float* __restrict__ po) {
    int bq = blockIdx.x;
    int bv = bq >> 2, q = bq & 3;
    int b = bv >> 3, v = bv & 7;
    int tid = threadIdx.x, h = tid >> 5, lane = tid & 31;
    __shared__ __align__(16) float sC[256];
    __shared__ float red8[8][8];
    int base = (h * Bv + b) * (Vv * NTB);     // 128 partials per (h,b)
    float m1 = g_am[base + lane], m2 = g_am[base + 32 + lane];
    float m3 = g_am[base + 64 + lane], m4 = g_am[base + 96 + lane];
    float M = warpMax(fmaxf(fmaxf(m1, m2), fmaxf(m3, m4)));
    float ss = g_as[base + lane] * __expf(m1 - M) + g_as[base + 32 + lane] * __expf(m2 - M)
             + g_as[base + 64 + lane] * __expf(m3 - M) + g_as[base + 96 + lane] * __expf(m4 - M);
    float S = warpSum(ss);
    float invS = 1.f / S;
    float sum = 0.f;
    #pragma unroll
    for (int tt = 0; tt < NTB; tt++) {
        int pp = base + v * NTB + tt;
        float mt = g_am[pp];
        sum += g_aacc[pp * 32 + lane] * __expf(mt - M);
    }
    sC[h * 32 + lane] = sum * invS;
    __syncthreads();

    // final_Q: this quarter owns po rows j = q*64 .. q*64+63; 4 threads split each dot
    int j = q * 64 + (tid >> 2), seg = tid & 3;
    const float4* wr = (const float4*)(po + (size_t)j * Dv + seg * 64);
    const float4* sc4 = (const float4*)(sC + seg * 64);
    float dot = 0.f;
    #pragma unroll
    for (int jj = 0; jj < 16; jj++) {
        float4 w4 = wr[jj], s4 = sc4[jj];
        dot += w4.x * s4.x + w4.y * s4.y + w4.z * s4.z + w4.w * s4.w;
    }
    dot += __shfl_xor_sync(0xffffffffu, dot, 1);
    dot += __shfl_xor_sync(0xffffffffu, dot, 2);
    float fqs = dot * SCALE_D;

    float p8[8] = {0, 0, 0, 0, 0, 0, 0, 0};
    if (seg == 0) {
        g_fQ[(size_t)bv * Dv + j] = fqs;      // pre-scaled for logits
        const float4* ar = (const float4*)(g_A8 + (512 + j) * 8);
        float4 a0 = ar[0], a1 = ar[1];
        p8[0] = fqs * a0.x; p8[1] = fqs * a0.y; p8[2] = fqs * a0.z; p8[3] = fqs * a0.w;
        p8[4] = fqs * a1.x; p8[5] = fqs * a1.y; p8[6] = fqs * a1.z; p8[7] = fqs * a1.w;
    }
    #pragma unroll
    for (int jj = 0; jj < 8; jj++) p8[jj] = warpSum(p8[jj]);
    if (lane == 0)
        #pragma unroll
        for (int jj = 0; jj < 8; jj++) red8[h][jj] = p8[jj];
    __syncthreads();
    if (tid < 8) {
        float s8 = 0.f;
        #pragma unroll
        for (int w = 0; w < 8; w++) s8 += red8[w][tid];
        g_QAp[bv * 32 + q * 8 + tid] = s8;    // deterministic quarter partial
    }
}

// ---------------- kD: logits. block=(tile8,b); warp per node; last block finalizes -------
__global__ void __launch_bounds__(256) kD(const float* __restrict__ lKs,
                                          const float* __restrict__ ndf,
                                          const void* __restrict__ mask,
                                          float* __restrict__ out, int out_size) {
    int t = blockIdx.x, b = blockIdx.y;
    int tid = threadIdx.x, w = tid >> 5, lane = tid & 31;
    // sFQ: xor-swizzled so 32 lanes' LDS.128 at lane*8(+sw) are phase-conflict-free
    __shared__ __align__(16) float sFQ[2048];
    __shared__ float sQA[64];
    __shared__ float sRm[8]; __shared__ int sRi[8]; __shared__ float sRs[8];
    __shared__ float sM; __shared__ int sI; __shared__ int sLast;

    #pragma unroll
    for (int i = 0; i < 8; i++) {
        int idx = i * 256 + tid;
        int vv = idx >> 8, d = idx & 255;
        int swc = ((d >> 5) & 1) * 4;                     // ((c>>2)&1)*4, c=d>>3
        int phys = vv * 256 + (d & ~7) + ((d & 4) ^ swc) + (d & 3);
        sFQ[phys] = g_fQ[(size_t)(b * Vv + vv) * Dv + d];
    }
    if (tid < 64) {
        int base = (b * Vv + (tid >> 3)) * 32 + (tid & 7);
        sQA[tid] = g_QAp[base] + g_QAp[base + 8] + g_QAp[base + 16] + g_QAp[base + 24];
    }
    __syncthreads();

    int n = t * 8 + w;                                    // 125*8 = 1000, always valid
    int sw = ((lane >> 2) & 1) * 4;
    const float4* kp = (const float4*)(lKs + ((size_t)b * Nv + n) * Dv + lane * 8);
    float4 g0 = kp[0], g1 = kp[1];                        // front-batched
    float dv[8];
    #pragma unroll
    for (int vv = 0; vv < 8; vv++) {
        const float* fb = &sFQ[vv * 256 + lane * 8];
        float4 lo = *(const float4*)&fb[sw];              // logical dims lane*8..+3
        float4 hi = *(const float4*)&fb[4 ^ sw];          // logical dims lane*8+4..+7
        dv[vv] = lo.x * g0.x + lo.y * g0.y + lo.z * g0.z + lo.w * g0.w
               + hi.x * g1.x + hi.y * g1.y + hi.z * g1.z + hi.w * g1.w;
    }
    // register-halving butterfly: lane L ends with dv[0] = total for v = L>>2
    {
        bool hb = (lane & 16) != 0;
        #pragma unroll
        for (int k = 0; k < 4; k++) {
            float send = hb ? dv[k] : dv[k + 4];
            float recv = __shfl_xor_sync(0xffffffffu, send, 16);
            dv[k] = (hb ? dv[k + 4] : dv[k]) + recv;
        }
        hb = (lane & 8) != 0;
        #pragma unroll
        for (int k = 0; k < 2; k++) {
            float send = hb ? dv[k] : dv[k + 2];
            float recv = __shfl_xor_sync(0xffffffffu, send, 8);
            dv[k] = (hb ? dv[k + 2] : dv[k]) + recv;
        }
        hb = (lane & 4) != 0;
        {
            float send = hb ? dv[0] : dv[1];
            float recv = __shfl_xor_sync(0xffffffffu, send, 4);
            dv[0] = (hb ? dv[1] : dv[0]) + recv;
        }
        dv[0] += __shfl_xor_sync(0xffffffffu, dv[0], 2);
        dv[0] += __shfl_xor_sync(0xffffffffu, dv[0], 1);
    }

    // lanes 0,4,...,28 handle v = lane>>2 for this node
    int mode = g_mask_mode;
    float val = -INFINITY; int bidx = INT_MAX;
    if ((lane & 3) == 0) {
        int vv = lane >> 2;
        int midx = (b * Vv + vv) * Nv + n;
        if (mask_at(mask, mode, midx)) {
            const float4* fp = (const float4*)(ndf + (size_t)midx * 8);
            float4 fA = fp[0], fB = fp[1];
            const float* qa = &sQA[vv * 8];
            float e = dv[0]
                    + qa[0] * fA.x + qa[1] * fA.y + qa[2] * fA.z + qa[3] * fA.w
                    + qa[4] * fB.x + qa[5] * fB.y + qa[6] * fB.z + qa[7] * fB.w;
            val = tanhf(e) * 10.0f;
            bidx = vv * Nv + n;
        }
    }
    float best = val; int bi = bidx;
    #pragma unroll
    for (int o = 16; o; o >>= 1) {
        float om = __shfl_xor_sync(0xffffffffu, best, o);
        int   oi = __shfl_xor_sync(0xffffffffu, bi, o);
        if (om > best || (om == best && oi < bi)) { best = om; bi = oi; }
    }
    if (lane == 0) { sRm[w] = best; sRi[w] = bi; }
    __syncthreads();
    if (tid == 0) {
        float M = -INFINITY; int I = INT_MAX;
        for (int i = 0; i < 8; i++)
            if (sRm[i] > M || (sRm[i] == M && sRi[i] < I)) { M = sRm[i]; I = sRi[i]; }
        sM = M; sI = I;
    }
    __syncthreads();
    float M = sM;
    float es = (val == -INFINITY) ? 0.f : __expf(val - M);
    es = warpSum(es);
    if (lane == 0) sRs[w] = es;
    __syncthreads();
    if (tid == 0) {
        float S = 0.f;
        for (int i = 0; i < 8; i++) S += sRs[i];
        int pi = b * 128 + t;
        g_lm[pi] = M; g_li[pi] = sI; g_ls[pi] = S;
        __threadfence();
        unsigned int old = atomicAdd(&g_cnt, 1u);
        sLast = (old == (NTD * Bv - 1)) ? 1 : 0;
    }
    __syncthreads();
    if (!sLast) return;
    __threadfence();   // acquire: make all blocks' partials visible

    // ---- final combine: warp w = batch; lane folds partials lane, +32, +64, +96 (<125) --
    float m2 = -INFINITY, s2 = 0.f; int ix = INT_MAX;
    if (lane < NTD) { m2 = g_lm[w * 128 + lane]; s2 = g_ls[w * 128 + lane]; ix = g_li[w * 128 + lane]; }
    #pragma unroll
    for (int ii = 1; ii < 4; ii++) {
        int i1 = lane + ii * 32;
        if (i1 < NTD) {
            float mB = g_lm[w * 128 + i1];
            float sB = g_ls[w * 128 + i1];
            int   iB = g_li[w * 128 + i1];
            float Mn = fmaxf(m2, mB);
            float sN = ((m2 == -INFINITY) ? 0.f : s2 * __expf(m2 - Mn))
                     + ((mB == -INFINITY) ? 0.f : sB * __expf(mB - Mn));
            if (mB > m2 || (mB == m2 && iB < ix)) ix = iB;
            m2 = Mn; s2 = sN;
        }
    }
    float M2 = m2; int I2 = ix;
    #pragma unroll
    for (int o = 16; o; o >>= 1) {
        float om = __shfl_xor_sync(0xffffffffu, M2, o);
        int   oi = __shfl_xor_sync(0xffffffffu, I2, o);
        if (om > M2 || (om == M2 && oi < I2)) { M2 = om; I2 = oi; }
    }
    float term = (m2 == -INFINITY) ? 0.f : s2 * __expf(m2 - M2);
    float S2 = warpSum(term);
    if (lane == 0) { sRs[w] = S2; sRi[w] = I2; }
    __syncthreads();
    if (tid < 8) {
        int op = sRi[tid];
        float Sb = sRs[tid];
        if (tid < out_size)      out[tid]      = (float)(op / Nv);
        if (8 + tid < out_size)  out[8 + tid]  = (float)(op % Nv);
        if (16 + tid < out_size) out[16 + tid] = -logf(Sb);
    }
    if (tid == 0 && out_size > 24) {
        float ent = 0.f;
        for (int i = 0; i < 8; i++) ent += logf(sRs[i]) / sRs[i];
        out[24] = ent;
    }
}

// ---------------- launch ----------------
extern "C" void kernel_launch(void* const* d_in, const int* in_sizes, int n_in,
                              void* d_out, int out_size) {
    (void)in_sizes; (void)n_in;
    const float* fixedc = (const float*)d_in[1];
    const float* prev   = (const float*)d_in[2];
    const float* ndf    = (const float*)d_in[3];
    const float* veh    = (const float*)d_in[4];
    const float* gVs    = (const float*)d_in[5];
    const float* gKs    = (const float*)d_in[6];
    const float* lKs    = (const float*)d_in[7];
    const void*  mask   = d_in[8];
    const float* pcs    = (const float*)d_in[9];
    const float* W1     = (const float*)d_in[10];
    const float* W2     = (const float*)d_in[11];
    const float* po     = (const float*)d_in[12];

    kA<<<D3 + 1 + 64, 256>>>(W1, W2, mask, fixedc, prev, veh, pcs);
    kB<<<dim3(NTB, Bv, Hv), 256>>>(gKs, gVs, ndf, mask);
    kC<<<256, 256>>>(po);
    kD<<<dim3(NTD, Bv), 256>>>(lKs, ndf, mask, (float*)d_out, out_size);
}